// round 9
// baseline (speedup 1.0000x reference)
#include <cuda_runtime.h>
#include <cuda_fp16.h>
#include <cstdint>

#define N_EDGES 100000
#define N_ANGLES 400000
#define N_CRYST 512
#define EPS 1e-5f
#define INV_SQRT_2 0.70710678118654752440f

typedef unsigned long long ull;
typedef unsigned int uint;

// ---------- scratch (static device globals; no runtime allocation) ----------
__device__ __half g_PQh[(size_t)N_EDGES * 512];   // P | Q  (fp16 storage)
__device__ __half g_hh[(size_t)N_ANGLES * 256];   // h      (fp16 storage)
__device__ float g_sum[N_CRYST * 256];
__device__ float g_sumsq[N_CRYST * 256];
__device__ int   g_cnt[N_CRYST];
__device__ float g_ca[N_CRYST * 256];
__device__ float g_cb[N_CRYST * 256];
__device__ float g_s[(size_t)N_EDGES * 128];
__device__ int   g_ecnt[N_EDGES];

__device__ __forceinline__ float silu_f(float x) { return x / (1.f + __expf(-x)); }
__device__ __forceinline__ uint tf32u(float x) {
    uint u; asm("cvt.rna.tf32.f32 %0, %1;" : "=r"(u) : "f"(x)); return u;
}
__device__ __forceinline__ void mma_tf32(float d[4], const uint a[4], const uint b[2]) {
    asm volatile(
        "mma.sync.aligned.m16n8k8.row.col.f32.tf32.tf32.f32 "
        "{%0,%1,%2,%3},{%4,%5,%6,%7},{%8,%9},{%0,%1,%2,%3};"
        : "+f"(d[0]), "+f"(d[1]), "+f"(d[2]), "+f"(d[3])
        : "r"(a[0]), "r"(a[1]), "r"(a[2]), "r"(a[3]), "r"(b[0]), "r"(b[1]));
}
__device__ __forceinline__ uint2 ldcs_u64(const void* p) {
    uint2 v; asm volatile("ld.global.cs.v2.u32 {%0,%1}, [%2];" : "=r"(v.x), "=r"(v.y) : "l"(p)); return v;
}
__device__ __forceinline__ float2 ldcs_f2(const void* p) {
    float2 v; asm volatile("ld.global.cs.v2.f32 {%0,%1}, [%2];" : "=f"(v.x), "=f"(v.y) : "l"(p)); return v;
}
__device__ __forceinline__ float4 ldcs_f4(const void* p) {
    float4 v; asm volatile("ld.global.cs.v4.f32 {%0,%1,%2,%3}, [%4];"
        : "=f"(v.x), "=f"(v.y), "=f"(v.z), "=f"(v.w) : "l"(p)); return v;
}
__device__ __forceinline__ void stcs_u32(void* p, uint v) {
    asm volatile("st.global.cs.b32 [%0], %1;" :: "l"(p), "r"(v) : "memory");
}
__device__ __forceinline__ void stcs_f2(void* p, float2 v) {
    asm volatile("st.global.cs.v2.f32 [%0], {%1,%2};" :: "l"(p), "f"(v.x), "f"(v.y) : "memory");
}
__device__ __forceinline__ uint h2u(__half2 h) { return *reinterpret_cast<uint*>(&h); }
__device__ __forceinline__ float2 u2f2(uint u) {
    __half2 h = *reinterpret_cast<__half2*>(&u); return __half22float2(h);
}

// ---------- K0: zero scratch ----------
__global__ void k_zero() {
    size_t i = (size_t)blockIdx.x * blockDim.x + threadIdx.x;
    size_t stride = (size_t)gridDim.x * blockDim.x;
    for (size_t t = i; t < (size_t)N_EDGES * 128; t += stride) g_s[t] = 0.f;
    for (size_t t = i; t < (size_t)N_EDGES; t += stride) g_ecnt[t] = 0;
    for (size_t t = i; t < (size_t)N_CRYST * 256; t += stride) { g_sum[t] = 0.f; g_sumsq[t] = 0.f; }
    for (size_t t = i; t < (size_t)N_CRYST; t += stride) g_cnt[t] = 0;
}

// ---- fragment-major staging helpers ----------------------------------------
__device__ __forceinline__ void stage_a_g(uint* buf, int KT, int row, int C, float v) {
    int mt = row >> 4, r = row & 15, kt = C >> 3, c = C & 7;
    int lane = (r & 7) * 4 + (c & 3);
    int slot = (r >> 3) + 2 * (c >> 2);
    buf[((mt * KT + kt) * 32 + lane) * 4 + slot] = tf32u(v);
}
__device__ __forceinline__ void stage_b_g(uint* buf, int KT, int nrow, int C, float v) {
    int nt = nrow >> 3, n = nrow & 7, kt = C >> 3, c = C & 7;
    int lane = n * 4 + (c & 3);
    int slot = c >> 2;
    buf[((nt * KT + kt) * 32 + lane) * 2 + slot] = tf32u(v);
}

// ============ tf32 MMA GEMM: BM=128, BN=128, BK=32, 256 thr (8 warps 4x2) ===
struct MmaSmem { uint a[128 * 32]; uint b[128 * 32]; };

__device__ __forceinline__ void mma_chunk(MmaSmem& sm, int wm, int wn, int lane,
                                          float acc[2][8][4]) {
#pragma unroll
    for (int kt = 0; kt < 4; kt++) {
        uint4 a0u = *reinterpret_cast<uint4*>(&sm.a[(((wm * 2 + 0) * 4 + kt) * 32 + lane) * 4]);
        uint4 a1u = *reinterpret_cast<uint4*>(&sm.a[(((wm * 2 + 1) * 4 + kt) * 32 + lane) * 4]);
        uint a0[4] = {a0u.x, a0u.y, a0u.z, a0u.w};
        uint a1[4] = {a1u.x, a1u.y, a1u.z, a1u.w};
#pragma unroll
        for (int j = 0; j < 8; j++) {
            uint2 bu = *reinterpret_cast<uint2*>(&sm.b[(((wn * 8 + j) * 4 + kt) * 32 + lane) * 2]);
            uint b[2] = {bu.x, bu.y};
            mma_tf32(acc[0][j], a0, b);
            mma_tf32(acc[1][j], a1, b);
        }
    }
}

// ---------- K1a: P/Q = nbr_fea @ W[:,64:192].T / W[:,192:320].T -------------
__global__ __launch_bounds__(256) void k_gemm_pq(const float* __restrict__ nbr,
                                                 const float* __restrict__ W) {
    __shared__ MmaSmem sm;
    int tid = threadIdx.x;
    int warp = tid >> 5, lane = tid & 31;
    int wm = warp >> 1, wn = warp & 1;
    int m_base = blockIdx.x * 128;
    int nb = blockIdx.y & 1, qsel = blockIdx.y >> 1;
    int koff = 64 + qsel * 128;
    int n_base = nb * 128;

    float acc[2][8][4];
#pragma unroll
    for (int i = 0; i < 2; i++)
#pragma unroll
        for (int j = 0; j < 8; j++)
#pragma unroll
            for (int k = 0; k < 4; k++) acc[i][j][k] = 0.f;

    for (int kc = 0; kc < 4; kc++) {
        int k0 = kc * 32;
#pragma unroll
        for (int it = 0; it < 4; it++) {
            int lin = it * 256 + tid;
            int row = lin >> 3, c4 = (lin & 7) * 4;
            int grow = m_base + row; if (grow >= N_EDGES) grow = N_EDGES - 1;
            float4 v = *reinterpret_cast<const float4*>(nbr + (size_t)grow * 128 + k0 + c4);
            stage_a_g(sm.a, 4, row, c4 + 0, v.x);
            stage_a_g(sm.a, 4, row, c4 + 1, v.y);
            stage_a_g(sm.a, 4, row, c4 + 2, v.z);
            stage_a_g(sm.a, 4, row, c4 + 3, v.w);
        }
#pragma unroll
        for (int it = 0; it < 4; it++) {
            int lin = it * 256 + tid;
            int row = lin >> 3, c4 = (lin & 7) * 4;
            float4 v = *reinterpret_cast<const float4*>(W + (size_t)(n_base + row) * 320 + koff + k0 + c4);
            stage_b_g(sm.b, 4, row, c4 + 0, v.x);
            stage_b_g(sm.b, 4, row, c4 + 1, v.y);
            stage_b_g(sm.b, 4, row, c4 + 2, v.z);
            stage_b_g(sm.b, 4, row, c4 + 3, v.w);
        }
        __syncthreads();
        mma_chunk(sm, wm, wn, lane, acc);
        __syncthreads();
    }
    int r = lane >> 2, cq = lane & 3;
#pragma unroll
    for (int mi = 0; mi < 2; mi++) {
        int R0 = m_base + wm * 32 + mi * 16 + r;
        int R1 = R0 + 8;
#pragma unroll
        for (int j = 0; j < 8; j++) {
            int gcol = qsel * 256 + n_base + wn * 64 + j * 8 + cq * 2;
            if (R0 < N_EDGES)
                *reinterpret_cast<__half2*>(&g_PQh[(size_t)R0 * 512 + gcol]) =
                    __floats2half2_rn(acc[mi][j][0], acc[mi][j][1]);
            if (R1 < N_EDGES)
                *reinterpret_cast<__half2*>(&g_PQh[(size_t)R1 * 512 + gcol]) =
                    __floats2half2_rn(acc[mi][j][2], acc[mi][j][3]);
        }
    }
}

// ---------- K1b: h = angle@Wa.T + P[i0] + Q[i1], FUSED crystal stats --------
// Block covers 128 angle rows x 128 cols. Sorted segments -> <=2 crystals
// typical; 2-slot smem accumulators, global-atomic fallback otherwise.
__global__ __launch_bounds__(256) void k_gemm_angle(const float* __restrict__ ang,
                                                    const float* __restrict__ W,
                                                    const int* __restrict__ nidx,
                                                    const int* __restrict__ seg) {
    extern __shared__ uint dsm[];
    uint* AF = dsm;            // 8192: A frags KT=8, 8 m-tiles
    uint* BF = dsm + 8192;     // 8192: B frags KT=8, 16 n-tiles
    float* sum_sm = (float*)(dsm + 16384);  // [2][128]
    float* sq_sm  = (float*)(dsm + 16640);  // [2][128]
    __shared__ int i0_sm[128], i1_sm[128], seg_sm[128];
    __shared__ int cnt_sm[2];
    int tid = threadIdx.x;
    int warp = tid >> 5, lane = tid & 31;
    int wm = warp >> 1, wn = warp & 1;
    int m_base = blockIdx.x * 128;
    int n_base = blockIdx.y * 128;

    if (tid < 128) {
        i0_sm[tid] = nidx[(m_base + tid) * 2 + 0];
        i1_sm[tid] = nidx[(m_base + tid) * 2 + 1];
        seg_sm[tid] = seg[m_base + tid];
    }
    sum_sm[tid] = 0.f;
    sq_sm[tid] = 0.f;
    if (tid < 2) cnt_sm[tid] = 0;

#pragma unroll
    for (int it = 0; it < 8; it++) {
        int lin = it * 256 + tid;
        int row = lin >> 4, c4 = (lin & 15) * 4;
        float4 v = ldcs_f4(ang + (size_t)(m_base + row) * 64 + c4);
        stage_a_g(AF, 8, row, c4 + 0, v.x);
        stage_a_g(AF, 8, row, c4 + 1, v.y);
        stage_a_g(AF, 8, row, c4 + 2, v.z);
        stage_a_g(AF, 8, row, c4 + 3, v.w);
    }
#pragma unroll
    for (int it = 0; it < 8; it++) {
        int lin = it * 256 + tid;
        int row = lin >> 4, c4 = (lin & 15) * 4;
        float4 v = *reinterpret_cast<const float4*>(W + (size_t)(n_base + row) * 320 + c4);
        stage_b_g(BF, 8, row, c4 + 0, v.x);
        stage_b_g(BF, 8, row, c4 + 1, v.y);
        stage_b_g(BF, 8, row, c4 + 2, v.z);
        stage_b_g(BF, 8, row, c4 + 3, v.w);
    }
    __syncthreads();

    float acc[2][8][4];
#pragma unroll
    for (int i = 0; i < 2; i++)
#pragma unroll
        for (int j = 0; j < 8; j++)
#pragma unroll
            for (int k = 0; k < 4; k++) acc[i][j][k] = 0.f;

#pragma unroll
    for (int kt = 0; kt < 8; kt++) {
        uint4 a0u = *reinterpret_cast<uint4*>(&AF[(((wm * 2 + 0) * 8 + kt) * 32 + lane) * 4]);
        uint4 a1u = *reinterpret_cast<uint4*>(&AF[(((wm * 2 + 1) * 8 + kt) * 32 + lane) * 4]);
        uint a0[4] = {a0u.x, a0u.y, a0u.z, a0u.w};
        uint a1[4] = {a1u.x, a1u.y, a1u.z, a1u.w};
#pragma unroll
        for (int j = 0; j < 8; j++) {
            uint2 bu = *reinterpret_cast<uint2*>(&BF[(((wn * 8 + j) * 8 + kt) * 32 + lane) * 2]);
            uint b[2] = {bu.x, bu.y};
            mma_tf32(acc[0][j], a0, b);
            mma_tf32(acc[1][j], a1, b);
        }
    }

    int seg_base = seg_sm[0];
    // counts (once per row; only y==0 blocks contribute)
    if (blockIdx.y == 0 && tid < 128) {
        int slot = seg_sm[tid] - seg_base;
        if (slot == 0 || slot == 1) atomicAdd(&cnt_sm[slot], 1);
        else atomicAdd(&g_cnt[seg_sm[tid]], 1);
    }

    // epilogue: gather P/Q, add, stream h out, accumulate stats
    int r = lane >> 2, cq = lane & 3;
#pragma unroll
    for (int mi = 0; mi < 2; mi++) {
#pragma unroll
        for (int half = 0; half < 2; half++) {
            int lr = wm * 32 + mi * 16 + r + half * 8;
            int R = m_base + lr;
            int i0 = i0_sm[lr], i1 = i1_sm[lr];
            int sg = seg_sm[lr];
            int slot = sg - seg_base;
            bool inblk = (slot == 0 || slot == 1);
            float* srow = &sum_sm[slot * 128];
            float* qrow = &sq_sm[slot * 128];
#pragma unroll
            for (int j = 0; j < 8; j++) {
                int gcol = n_base + wn * 64 + j * 8 + cq * 2;
                int lcol = gcol - n_base;
                float2 p = __half22float2(*reinterpret_cast<const __half2*>(&g_PQh[(size_t)i0 * 512 + gcol]));
                float2 q = __half22float2(*reinterpret_cast<const __half2*>(&g_PQh[(size_t)i1 * 512 + 256 + gcol]));
                float a0 = acc[mi][j][half * 2 + 0], a1 = acc[mi][j][half * 2 + 1];
                float v0 = a0 + p.x + q.x;
                float v1 = a1 + p.y + q.y;
                stcs_u32(&g_hh[(size_t)R * 256 + gcol], h2u(__floats2half2_rn(v0, v1)));
                if (inblk) {
                    atomicAdd(&srow[lcol], v0);
                    atomicAdd(&srow[lcol + 1], v1);
                    atomicAdd(&qrow[lcol], v0 * v0);
                    atomicAdd(&qrow[lcol + 1], v1 * v1);
                } else {
                    atomicAdd(&g_sum[sg * 256 + gcol], v0);
                    atomicAdd(&g_sum[sg * 256 + gcol + 1], v1);
                    atomicAdd(&g_sumsq[sg * 256 + gcol], v0 * v0);
                    atomicAdd(&g_sumsq[sg * 256 + gcol + 1], v1 * v1);
                }
            }
        }
    }
    __syncthreads();
    // flush: 256 threads cover 2 slots x 128 cols
    {
        int slot = tid >> 7, col = tid & 127;
        int sg = seg_base + slot;
        bool valid = (slot == 0) || (sg < N_CRYST && sg != seg_base);
        if (valid) {
            float sv = sum_sm[slot * 128 + col];
            float qv = sq_sm[slot * 128 + col];
            if (sv != 0.f || qv != 0.f) {
                atomicAdd(&g_sum[sg * 256 + n_base + col], sv);
                atomicAdd(&g_sumsq[sg * 256 + n_base + col], qv);
            }
        }
        if (blockIdx.y == 0 && col == 0 && valid && cnt_sm[slot] > 0)
            atomicAdd(&g_cnt[sg], cnt_sm[slot]);
    }
}

// ---------- K3: crystal-norm affine coefficients ----------------------------
__global__ void k_finalize(const float* __restrict__ gamma, const float* __restrict__ beta) {
    int c = blockIdx.x, n = threadIdx.x;
    float cnt = fmaxf((float)g_cnt[c], 1.f);
    float mean = g_sum[c * 256 + n] / cnt;
    float var = fmaxf(g_sumsq[c * 256 + n] / cnt - mean * mean, 0.f);
    float a = gamma[n] * rsqrtf(var + EPS);
    g_ca[c * 256 + n] = a;
    g_cb[c * 256 + n] = beta[n] - mean * a;
}

// ---------- K4: per-angle msg + scatter; block-cached ca/cb -----------------
__global__ __launch_bounds__(256) void k_msg(const int* __restrict__ seg,
                                             const int* __restrict__ nidx,
                                             const float* __restrict__ Wm,
                                             const float* __restrict__ lng,
                                             const float* __restrict__ lnb) {
    __shared__ float ca_sm[256], cb_sm[256];
    __shared__ int sg_sm[8];
    int tid = threadIdx.x;
    int lane = tid & 31;
    int w = tid >> 5;
    int row_base = blockIdx.x * 8;
    int row = row_base + w;
    if (tid < 8) sg_sm[tid] = seg[row_base + tid];
    __syncthreads();
    int sg0 = sg_sm[0];
    ca_sm[tid] = g_ca[(size_t)sg0 * 256 + tid];
    cb_sm[tid] = g_cb[(size_t)sg0 * 256 + tid];
    __syncthreads();
    int sg = sg_sm[w];
    const float4* cap = (sg == sg0) ? reinterpret_cast<const float4*>(ca_sm)
                                    : reinterpret_cast<const float4*>(&g_ca[(size_t)sg * 256]);
    const float4* cbp = (sg == sg0) ? reinterpret_cast<const float4*>(cb_sm)
                                    : reinterpret_cast<const float4*>(&g_cb[(size_t)sg * 256]);

    const char* hbase = (const char*)&g_hh[(size_t)row * 256];
    uint2 hcu = ldcs_u64(hbase + lane * 8);
    uint2 hfu = ldcs_u64(hbase + 256 + lane * 8);
    float2 c01 = u2f2(hcu.x), c23 = u2f2(hcu.y);
    float2 f01 = u2f2(hfu.x), f23 = u2f2(hfu.y);
    float4 hc = {c01.x, c01.y, c23.x, c23.y};
    float4 hf = {f01.x, f01.y, f23.x, f23.y};
    float4 ac = cap[lane], af = cap[32 + lane];
    float4 bc = cbp[lane], bf = cbp[32 + lane];
    float4 core, filt;
    core.x = hc.x * ac.x + bc.x; core.y = hc.y * ac.y + bc.y;
    core.z = hc.z * ac.z + bc.z; core.w = hc.w * ac.w + bc.w;
    filt.x = hf.x * af.x + bf.x; filt.y = hf.y * af.y + bf.y;
    filt.z = hf.z * af.z + bf.z; filt.w = hf.w * af.w + bf.w;
    float s1 = core.x + core.y + core.z + core.w;
    float s2 = core.x * core.x + core.y * core.y + core.z * core.z + core.w * core.w;
#pragma unroll
    for (int off = 16; off >= 1; off >>= 1) {
        s1 += __shfl_xor_sync(0xffffffffu, s1, off);
        s2 += __shfl_xor_sync(0xffffffffu, s2, off);
    }
    float mean = s1 * (1.f / 128.f);
    float var = fmaxf(s2 * (1.f / 128.f) - mean * mean, 0.f);
    float rstd = rsqrtf(var + EPS);
    float4 g4 = reinterpret_cast<const float4*>(lng)[lane];
    float4 b4 = reinterpret_cast<const float4*>(lnb)[lane];
    float4 sl;
    sl.x = silu_f((core.x - mean) * rstd * g4.x + b4.x);
    sl.y = silu_f((core.y - mean) * rstd * g4.y + b4.y);
    sl.z = silu_f((core.z - mean) * rstd * g4.z + b4.z);
    sl.w = silu_f((core.w - mean) * rstd * g4.w + b4.w);
    float4 wm = reinterpret_cast<const float4*>(Wm)[lane];
    float gp = filt.x * wm.x + filt.y * wm.y + filt.z * wm.z + filt.w * wm.w;
#pragma unroll
    for (int off = 16; off >= 1; off >>= 1) gp += __shfl_xor_sync(0xffffffffu, gp, off);
    float gate = 1.f / (1.f + __expf(-gp));
    float4 msg = {gate * sl.x, gate * sl.y, gate * sl.z, gate * sl.w};
    int src = nidx[row * 2];
    float* dst = &g_s[(size_t)src * 128 + lane * 4];
    asm volatile("red.global.add.v4.f32 [%0], {%1,%2,%3,%4};"
                 :: "l"(dst), "f"(msg.x), "f"(msg.y), "f"(msg.z), "f"(msg.w) : "memory");
    if (lane == 0) atomicAdd(&g_ecnt[src], 1);
}

// ---------- K5: per-edge LN2 + two residual MLPs, tf32 tensor cores ---------
__global__ __launch_bounds__(512) void k_edge(const float* __restrict__ nbr,
                       const float* __restrict__ ln2g, const float* __restrict__ ln2b,
                       const float* __restrict__ W1a, const float* __restrict__ b1a,
                       const float* __restrict__ W2a, const float* __restrict__ b2a,
                       const float* __restrict__ W1b, const float* __restrict__ b1b,
                       const float* __restrict__ W2b, const float* __restrict__ b2b,
                       float* __restrict__ out) {
    extern __shared__ uint usm[];
    uint* W1AF = usm;
    uint* W2AF = usm + 8192;
    uint* W1BF = usm + 16384;
    uint* W2BF = usm + 24576;
    uint* XF   = usm + 32768;
    uint* H1F  = usm + 36864;
    float* x_sm = (float*)(usm + 38912);
    float* bias = (float*)(usm + 43008);
    float* b1as = bias;
    float* b2as = bias + 64;
    float* b1bs = bias + 192;
    float* b2bs = bias + 256;
    float* g2s  = bias + 384;
    float* bb2s = bias + 512;

    int tid = threadIdx.x;
    int wid = tid >> 5, lane = tid & 31;
    int r = lane >> 2, cq = lane & 3;

    for (int i = tid; i < 8192; i += 512) {
        int j = i >> 7, d = i & 127;
        stage_b_g(W1AF, 16, j, d, W1a[i]);
        stage_b_g(W1BF, 16, j, d, W1b[i]);
        int d2 = i >> 6, j2 = i & 63;
        stage_b_g(W2AF, 8, d2, j2, W2a[i]);
        stage_b_g(W2BF, 8, d2, j2, W2b[i]);
    }
    if (tid < 64) { b1as[tid] = b1a[tid]; bias[192 + tid] = b1b[tid]; }
    else if (tid >= 128 && tid < 256) {
        int t = tid - 128;
        b2as[t] = b2a[t]; b2bs[t] = b2b[t]; g2s[t] = ln2g[t]; bb2s[t] = ln2b[t];
    }
    __syncthreads();

    int mt = wid >> 3;
    int ntw = wid & 7;

    for (int grp = blockIdx.x; grp < N_EDGES / 32; grp += gridDim.x) {
        int e_base = grp * 32;
        {
            int eL = tid >> 4, l16 = tid & 15;
            int e = e_base + eL;
            float inv = 1.f / fmaxf((float)g_ecnt[e], 1.f);
            float4 v0 = ldcs_f4(&g_s[(size_t)e * 128 + l16 * 8]);
            float4 v1 = ldcs_f4(&g_s[(size_t)e * 128 + l16 * 8 + 4]);
            float vals[8] = {v0.x * inv, v0.y * inv, v0.z * inv, v0.w * inv,
                             v1.x * inv, v1.y * inv, v1.z * inv, v1.w * inv};
            float s1 = 0.f, s2 = 0.f;
#pragma unroll
            for (int k = 0; k < 8; k++) { s1 += vals[k]; s2 += vals[k] * vals[k]; }
#pragma unroll
            for (int off = 8; off >= 1; off >>= 1) {
                s1 += __shfl_xor_sync(0xffffffffu, s1, off);
                s2 += __shfl_xor_sync(0xffffffffu, s2, off);
            }
            float mean = s1 * (1.f / 128.f);
            float var = fmaxf(s2 * (1.f / 128.f) - mean * mean, 0.f);
            float rstd = rsqrtf(var + EPS);
            int d0 = l16 * 8;
#pragma unroll
            for (int k = 0; k < 8; k++) {
                float xv = (vals[k] - mean) * rstd * g2s[d0 + k] + bb2s[d0 + k];
                x_sm[eL * 128 + d0 + k] = xv;
                stage_a_g(XF, 16, eL, d0 + k, xv);
            }
        }
        __syncthreads();
        {
            float c[4] = {0.f, 0.f, 0.f, 0.f};
#pragma unroll
            for (int kt = 0; kt < 16; kt++) {
                uint4 au = *reinterpret_cast<uint4*>(&XF[((mt * 16 + kt) * 32 + lane) * 4]);
                uint a[4] = {au.x, au.y, au.z, au.w};
                uint2 bu = *reinterpret_cast<uint2*>(&W1AF[((ntw * 16 + kt) * 32 + lane) * 2]);
                uint b[2] = {bu.x, bu.y};
                mma_tf32(c, a, b);
            }
            int col = ntw * 8 + cq * 2;
            int row0 = mt * 16 + r, row1 = row0 + 8;
            stage_a_g(H1F, 8, row0, col,     silu_f(c[0] + b1as[col]));
            stage_a_g(H1F, 8, row0, col + 1, silu_f(c[1] + b1as[col + 1]));
            stage_a_g(H1F, 8, row1, col,     silu_f(c[2] + b1as[col]));
            stage_a_g(H1F, 8, row1, col + 1, silu_f(c[3] + b1as[col + 1]));
        }
        __syncthreads();
        {
#pragma unroll
            for (int t = 0; t < 2; t++) {
                int nt2 = ntw + t * 8;
                float c[4] = {0.f, 0.f, 0.f, 0.f};
#pragma unroll
                for (int kt = 0; kt < 8; kt++) {
                    uint4 au = *reinterpret_cast<uint4*>(&H1F[((mt * 8 + kt) * 32 + lane) * 4]);
                    uint a[4] = {au.x, au.y, au.z, au.w};
                    uint2 bu = *reinterpret_cast<uint2*>(&W2AF[((nt2 * 8 + kt) * 32 + lane) * 2]);
                    uint b[2] = {bu.x, bu.y};
                    mma_tf32(c, a, b);
                }
                int col = nt2 * 8 + cq * 2;
                int row0 = mt * 16 + r, row1 = row0 + 8;
                float n00 = x_sm[row0 * 128 + col]     + c[0] + b2as[col];
                float n01 = x_sm[row0 * 128 + col + 1] + c[1] + b2as[col + 1];
                float n10 = x_sm[row1 * 128 + col]     + c[2] + b2as[col];
                float n11 = x_sm[row1 * 128 + col + 1] + c[3] + b2as[col + 1];
                x_sm[row0 * 128 + col] = n00;     x_sm[row0 * 128 + col + 1] = n01;
                x_sm[row1 * 128 + col] = n10;     x_sm[row1 * 128 + col + 1] = n11;
                stage_a_g(XF, 16, row0, col, n00); stage_a_g(XF, 16, row0, col + 1, n01);
                stage_a_g(XF, 16, row1, col, n10); stage_a_g(XF, 16, row1, col + 1, n11);
            }
        }
        __syncthreads();
        {
            float c[4] = {0.f, 0.f, 0.f, 0.f};
#pragma unroll
            for (int kt = 0; kt < 16; kt++) {
                uint4 au = *reinterpret_cast<uint4*>(&XF[((mt * 16 + kt) * 32 + lane) * 4]);
                uint a[4] = {au.x, au.y, au.z, au.w};
                uint2 bu = *reinterpret_cast<uint2*>(&W1BF[((ntw * 16 + kt) * 32 + lane) * 2]);
                uint b[2] = {bu.x, bu.y};
                mma_tf32(c, a, b);
            }
            int col = ntw * 8 + cq * 2;
            int row0 = mt * 16 + r, row1 = row0 + 8;
            stage_a_g(H1F, 8, row0, col,     silu_f(c[0] + bias[192 + col]));
            stage_a_g(H1F, 8, row0, col + 1, silu_f(c[1] + bias[192 + col + 1]));
            stage_a_g(H1F, 8, row1, col,     silu_f(c[2] + bias[192 + col]));
            stage_a_g(H1F, 8, row1, col + 1, silu_f(c[3] + bias[192 + col + 1]));
        }
        __syncthreads();
        {
#pragma unroll
            for (int t = 0; t < 2; t++) {
                int nt2 = ntw + t * 8;
                float c[4] = {0.f, 0.f, 0.f, 0.f};
#pragma unroll
                for (int kt = 0; kt < 8; kt++) {
                    uint4 au = *reinterpret_cast<uint4*>(&H1F[((mt * 8 + kt) * 32 + lane) * 4]);
                    uint a[4] = {au.x, au.y, au.z, au.w};
                    uint2 bu = *reinterpret_cast<uint2*>(&W2BF[((nt2 * 8 + kt) * 32 + lane) * 2]);
                    uint b[2] = {bu.x, bu.y};
                    mma_tf32(c, a, b);
                }
                int col = nt2 * 8 + cq * 2;
                int row0 = mt * 16 + r, row1 = row0 + 8;
                int e0 = e_base + row0, e1 = e_base + row1;
                float f00 = x_sm[row0 * 128 + col]     + c[0] + b2bs[col];
                float f01 = x_sm[row0 * 128 + col + 1] + c[1] + b2bs[col + 1];
                float f10 = x_sm[row1 * 128 + col]     + c[2] + b2bs[col];
                float f11 = x_sm[row1 * 128 + col + 1] + c[3] + b2bs[col + 1];
                float2 nb0 = ldcs_f2(&nbr[(size_t)e0 * 128 + col]);
                float2 nb1 = ldcs_f2(&nbr[(size_t)e1 * 128 + col]);
                float2 o0 = {INV_SQRT_2 * (nb0.x + f00), INV_SQRT_2 * (nb0.y + f01)};
                float2 o1 = {INV_SQRT_2 * (nb1.x + f10), INV_SQRT_2 * (nb1.y + f11)};
                stcs_f2(&out[(size_t)e0 * 128 + col], o0);
                stcs_f2(&out[(size_t)e1 * 128 + col], o1);
            }
        }
        __syncthreads();
    }
}

// ---------- launch ----------------------------------------------------------
extern "C" void kernel_launch(void* const* d_in, const int* in_sizes, int n_in,
                              void* d_out, int out_size) {
    const float* nbr_fea   = (const float*)d_in[0];
    const float* angle_fea = (const float*)d_in[1];
    const int*   nidx      = (const int*)d_in[2];
    const int*   cai       = (const int*)d_in[4];
    const float* W_full    = (const float*)d_in[5];
    const float* W_mask    = (const float*)d_in[6];
    const float* cn_gamma  = (const float*)d_in[7];
    const float* cn_beta   = (const float*)d_in[8];
    const float* ln_core_g = (const float*)d_in[9];
    const float* ln_core_b = (const float*)d_in[10];
    const float* ln2_g     = (const float*)d_in[11];
    const float* ln2_b     = (const float*)d_in[12];
    const float* res_W1a   = (const float*)d_in[13];
    const float* res_b1a   = (const float*)d_in[14];
    const float* res_W2a   = (const float*)d_in[15];
    const float* res_b2a   = (const float*)d_in[16];
    const float* res_W1b   = (const float*)d_in[17];
    const float* res_b1b   = (const float*)d_in[18];
    const float* res_W2b   = (const float*)d_in[19];
    const float* res_b2b   = (const float*)d_in[20];
    float* out = (float*)d_out;

    static bool attr_set = false;
    if (!attr_set) {
        cudaFuncSetAttribute(k_edge, cudaFuncAttributeMaxDynamicSharedMemorySize, 176 * 1024);
        cudaFuncSetAttribute(k_gemm_angle, cudaFuncAttributeMaxDynamicSharedMemorySize, 72 * 1024);
        attr_set = true;
    }

    k_zero<<<1024, 256>>>();
    k_gemm_pq<<<dim3((N_EDGES + 127) / 128, 4), 256>>>(nbr_fea, W_full);
    k_gemm_angle<<<dim3(N_ANGLES / 128, 2), 256, 67584>>>(angle_fea, W_full, nidx, cai);
    k_finalize<<<N_CRYST, 256>>>(cn_gamma, cn_beta);
    k_msg<<<N_ANGLES / 8, 256>>>(cai, nidx, W_mask, ln_core_g, ln_core_b);
    k_edge<<<148, 512, 43648 * sizeof(float)>>>(nbr_fea, ln2_g, ln2_b,
                                                res_W1a, res_b1a, res_W2a, res_b2a,
                                                res_W1b, res_b1b, res_W2b, res_b2b, out);
}

// round 10
// speedup vs baseline: 2.3350x; 2.3350x over previous
#include <cuda_runtime.h>
#include <cuda_fp16.h>
#include <cstdint>

#define N_EDGES 100000
#define N_ANGLES 400000
#define N_CRYST 512
#define EPS 1e-5f
#define INV_SQRT_2 0.70710678118654752440f

typedef unsigned long long ull;
typedef unsigned int uint;

// ---------- scratch (static device globals; no runtime allocation) ----------
__device__ __half g_PQh[(size_t)N_EDGES * 512];   // P | Q  (fp16 storage)
__device__ __half g_hh[(size_t)N_ANGLES * 256];   // h      (fp16 storage)
__device__ float g_sum[N_CRYST * 256];
__device__ float g_sumsq[N_CRYST * 256];
__device__ int   g_cnt[N_CRYST];
__device__ float g_ca[N_CRYST * 256];
__device__ float g_cb[N_CRYST * 256];
__device__ float g_s[(size_t)N_EDGES * 128];
__device__ int   g_ecnt[N_EDGES];

__device__ __forceinline__ float silu_f(float x) { return x / (1.f + __expf(-x)); }
__device__ __forceinline__ uint tf32u(float x) {
    uint u; asm("cvt.rna.tf32.f32 %0, %1;" : "=r"(u) : "f"(x)); return u;
}
__device__ __forceinline__ void mma_tf32(float d[4], const uint a[4], const uint b[2]) {
    asm volatile(
        "mma.sync.aligned.m16n8k8.row.col.f32.tf32.tf32.f32 "
        "{%0,%1,%2,%3},{%4,%5,%6,%7},{%8,%9},{%0,%1,%2,%3};"
        : "+f"(d[0]), "+f"(d[1]), "+f"(d[2]), "+f"(d[3])
        : "r"(a[0]), "r"(a[1]), "r"(a[2]), "r"(a[3]), "r"(b[0]), "r"(b[1]));
}
__device__ __forceinline__ uint ldcs_u32(const void* p) {
    uint v; asm volatile("ld.global.cs.b32 %0, [%1];" : "=r"(v) : "l"(p)); return v;
}
__device__ __forceinline__ uint2 ldcs_u64(const void* p) {
    uint2 v; asm volatile("ld.global.cs.v2.u32 {%0,%1}, [%2];" : "=r"(v.x), "=r"(v.y) : "l"(p)); return v;
}
__device__ __forceinline__ float2 ldcs_f2(const void* p) {
    float2 v; asm volatile("ld.global.cs.v2.f32 {%0,%1}, [%2];" : "=f"(v.x), "=f"(v.y) : "l"(p)); return v;
}
__device__ __forceinline__ float4 ldcs_f4(const void* p) {
    float4 v; asm volatile("ld.global.cs.v4.f32 {%0,%1,%2,%3}, [%4];"
        : "=f"(v.x), "=f"(v.y), "=f"(v.z), "=f"(v.w) : "l"(p)); return v;
}
__device__ __forceinline__ void stcs_u32(void* p, uint v) {
    asm volatile("st.global.cs.b32 [%0], %1;" :: "l"(p), "r"(v) : "memory");
}
__device__ __forceinline__ void stcs_f2(void* p, float2 v) {
    asm volatile("st.global.cs.v2.f32 [%0], {%1,%2};" :: "l"(p), "f"(v.x), "f"(v.y) : "memory");
}
__device__ __forceinline__ uint h2u(__half2 h) { return *reinterpret_cast<uint*>(&h); }
__device__ __forceinline__ float2 u2f2(uint u) {
    __half2 h = *reinterpret_cast<__half2*>(&u); return __half22float2(h);
}

// ---------- K0: zero scratch ----------
__global__ void k_zero() {
    size_t i = (size_t)blockIdx.x * blockDim.x + threadIdx.x;
    size_t stride = (size_t)gridDim.x * blockDim.x;
    for (size_t t = i; t < (size_t)N_EDGES * 128; t += stride) g_s[t] = 0.f;
    for (size_t t = i; t < (size_t)N_EDGES; t += stride) g_ecnt[t] = 0;
    for (size_t t = i; t < (size_t)N_CRYST * 256; t += stride) { g_sum[t] = 0.f; g_sumsq[t] = 0.f; }
    for (size_t t = i; t < (size_t)N_CRYST; t += stride) g_cnt[t] = 0;
}

// ---- fragment-major staging helpers ----------------------------------------
__device__ __forceinline__ void stage_a_g(uint* buf, int KT, int row, int C, float v) {
    int mt = row >> 4, r = row & 15, kt = C >> 3, c = C & 7;
    int lane = (r & 7) * 4 + (c & 3);
    int slot = (r >> 3) + 2 * (c >> 2);
    buf[((mt * KT + kt) * 32 + lane) * 4 + slot] = tf32u(v);
}
__device__ __forceinline__ void stage_b_g(uint* buf, int KT, int nrow, int C, float v) {
    int nt = nrow >> 3, n = nrow & 7, kt = C >> 3, c = C & 7;
    int lane = n * 4 + (c & 3);
    int slot = c >> 2;
    buf[((nt * KT + kt) * 32 + lane) * 2 + slot] = tf32u(v);
}

// ============ tf32 MMA GEMM: BM=128, BN=128, BK=32, 256 thr (8 warps 4x2) ===
struct MmaSmem { uint a[128 * 32]; uint b[128 * 32]; };

__device__ __forceinline__ void mma_chunk(MmaSmem& sm, int wm, int wn, int lane,
                                          float acc[2][8][4]) {
#pragma unroll
    for (int kt = 0; kt < 4; kt++) {
        uint4 a0u = *reinterpret_cast<uint4*>(&sm.a[(((wm * 2 + 0) * 4 + kt) * 32 + lane) * 4]);
        uint4 a1u = *reinterpret_cast<uint4*>(&sm.a[(((wm * 2 + 1) * 4 + kt) * 32 + lane) * 4]);
        uint a0[4] = {a0u.x, a0u.y, a0u.z, a0u.w};
        uint a1[4] = {a1u.x, a1u.y, a1u.z, a1u.w};
#pragma unroll
        for (int j = 0; j < 8; j++) {
            uint2 bu = *reinterpret_cast<uint2*>(&sm.b[(((wn * 8 + j) * 4 + kt) * 32 + lane) * 2]);
            uint b[2] = {bu.x, bu.y};
            mma_tf32(acc[0][j], a0, b);
            mma_tf32(acc[1][j], a1, b);
        }
    }
}

// ---------- K1a: P/Q = nbr_fea @ W[:,64:192].T / W[:,192:320].T -------------
__global__ __launch_bounds__(256) void k_gemm_pq(const float* __restrict__ nbr,
                                                 const float* __restrict__ W) {
    __shared__ MmaSmem sm;
    int tid = threadIdx.x;
    int warp = tid >> 5, lane = tid & 31;
    int wm = warp >> 1, wn = warp & 1;
    int m_base = blockIdx.x * 128;
    int nb = blockIdx.y & 1, qsel = blockIdx.y >> 1;
    int koff = 64 + qsel * 128;
    int n_base = nb * 128;

    float acc[2][8][4];
#pragma unroll
    for (int i = 0; i < 2; i++)
#pragma unroll
        for (int j = 0; j < 8; j++)
#pragma unroll
            for (int k = 0; k < 4; k++) acc[i][j][k] = 0.f;

    for (int kc = 0; kc < 4; kc++) {
        int k0 = kc * 32;
#pragma unroll
        for (int it = 0; it < 4; it++) {
            int lin = it * 256 + tid;
            int row = lin >> 3, c4 = (lin & 7) * 4;
            int grow = m_base + row; if (grow >= N_EDGES) grow = N_EDGES - 1;
            float4 v = *reinterpret_cast<const float4*>(nbr + (size_t)grow * 128 + k0 + c4);
            stage_a_g(sm.a, 4, row, c4 + 0, v.x);
            stage_a_g(sm.a, 4, row, c4 + 1, v.y);
            stage_a_g(sm.a, 4, row, c4 + 2, v.z);
            stage_a_g(sm.a, 4, row, c4 + 3, v.w);
        }
#pragma unroll
        for (int it = 0; it < 4; it++) {
            int lin = it * 256 + tid;
            int row = lin >> 3, c4 = (lin & 7) * 4;
            float4 v = *reinterpret_cast<const float4*>(W + (size_t)(n_base + row) * 320 + koff + k0 + c4);
            stage_b_g(sm.b, 4, row, c4 + 0, v.x);
            stage_b_g(sm.b, 4, row, c4 + 1, v.y);
            stage_b_g(sm.b, 4, row, c4 + 2, v.z);
            stage_b_g(sm.b, 4, row, c4 + 3, v.w);
        }
        __syncthreads();
        mma_chunk(sm, wm, wn, lane, acc);
        __syncthreads();
    }
    int r = lane >> 2, cq = lane & 3;
#pragma unroll
    for (int mi = 0; mi < 2; mi++) {
        int R0 = m_base + wm * 32 + mi * 16 + r;
        int R1 = R0 + 8;
#pragma unroll
        for (int j = 0; j < 8; j++) {
            int gcol = qsel * 256 + n_base + wn * 64 + j * 8 + cq * 2;
            if (R0 < N_EDGES)
                *reinterpret_cast<__half2*>(&g_PQh[(size_t)R0 * 512 + gcol]) =
                    __floats2half2_rn(acc[mi][j][0], acc[mi][j][1]);
            if (R1 < N_EDGES)
                *reinterpret_cast<__half2*>(&g_PQh[(size_t)R1 * 512 + gcol]) =
                    __floats2half2_rn(acc[mi][j][2], acc[mi][j][3]);
        }
    }
}

// ---------- K1b: h = angle@Wa.T + P[i0] + Q[i1] (single-stage, K=64) --------
__global__ __launch_bounds__(256) void k_gemm_angle(const float* __restrict__ ang,
                                                    const float* __restrict__ W,
                                                    const int* __restrict__ nidx) {
    extern __shared__ uint dsm[];
    uint* AF = dsm;            // KT=8, 8 m-tiles
    uint* BF = dsm + 8192;     // KT=8, 16 n-tiles
    __shared__ int i0_sm[128], i1_sm[128];
    int tid = threadIdx.x;
    int warp = tid >> 5, lane = tid & 31;
    int wm = warp >> 1, wn = warp & 1;
    int m_base = blockIdx.x * 128;
    int n_base = blockIdx.y * 128;

    if (tid < 128) {
        i0_sm[tid] = nidx[(m_base + tid) * 2 + 0];
        i1_sm[tid] = nidx[(m_base + tid) * 2 + 1];
    }

#pragma unroll
    for (int it = 0; it < 8; it++) {
        int lin = it * 256 + tid;
        int row = lin >> 4, c4 = (lin & 15) * 4;
        float4 v = ldcs_f4(ang + (size_t)(m_base + row) * 64 + c4);
        stage_a_g(AF, 8, row, c4 + 0, v.x);
        stage_a_g(AF, 8, row, c4 + 1, v.y);
        stage_a_g(AF, 8, row, c4 + 2, v.z);
        stage_a_g(AF, 8, row, c4 + 3, v.w);
    }
#pragma unroll
    for (int it = 0; it < 8; it++) {
        int lin = it * 256 + tid;
        int row = lin >> 4, c4 = (lin & 15) * 4;
        float4 v = *reinterpret_cast<const float4*>(W + (size_t)(n_base + row) * 320 + c4);
        stage_b_g(BF, 8, row, c4 + 0, v.x);
        stage_b_g(BF, 8, row, c4 + 1, v.y);
        stage_b_g(BF, 8, row, c4 + 2, v.z);
        stage_b_g(BF, 8, row, c4 + 3, v.w);
    }
    __syncthreads();

    float acc[2][8][4];
#pragma unroll
    for (int i = 0; i < 2; i++)
#pragma unroll
        for (int j = 0; j < 8; j++)
#pragma unroll
            for (int k = 0; k < 4; k++) acc[i][j][k] = 0.f;

#pragma unroll
    for (int kt = 0; kt < 8; kt++) {
        uint4 a0u = *reinterpret_cast<uint4*>(&AF[(((wm * 2 + 0) * 8 + kt) * 32 + lane) * 4]);
        uint4 a1u = *reinterpret_cast<uint4*>(&AF[(((wm * 2 + 1) * 8 + kt) * 32 + lane) * 4]);
        uint a0[4] = {a0u.x, a0u.y, a0u.z, a0u.w};
        uint a1[4] = {a1u.x, a1u.y, a1u.z, a1u.w};
#pragma unroll
        for (int j = 0; j < 8; j++) {
            uint2 bu = *reinterpret_cast<uint2*>(&BF[(((wn * 8 + j) * 8 + kt) * 32 + lane) * 2]);
            uint b[2] = {bu.x, bu.y};
            mma_tf32(acc[0][j], a0, b);
            mma_tf32(acc[1][j], a1, b);
        }
    }

    int r = lane >> 2, cq = lane & 3;
#pragma unroll
    for (int mi = 0; mi < 2; mi++) {
        int lr0 = wm * 32 + mi * 16 + r;
        int lr1 = lr0 + 8;
        int R0 = m_base + lr0, R1 = m_base + lr1;
        int i0a = i0_sm[lr0], i1a = i1_sm[lr0];
        int i0b = i0_sm[lr1], i1b = i1_sm[lr1];
#pragma unroll
        for (int j = 0; j < 8; j++) {
            int gcol = n_base + wn * 64 + j * 8 + cq * 2;
            float2 p0 = __half22float2(*reinterpret_cast<const __half2*>(&g_PQh[(size_t)i0a * 512 + gcol]));
            float2 q0 = __half22float2(*reinterpret_cast<const __half2*>(&g_PQh[(size_t)i1a * 512 + 256 + gcol]));
            stcs_u32(&g_hh[(size_t)R0 * 256 + gcol],
                     h2u(__floats2half2_rn(acc[mi][j][0] + p0.x + q0.x, acc[mi][j][1] + p0.y + q0.y)));
            float2 p1 = __half22float2(*reinterpret_cast<const __half2*>(&g_PQh[(size_t)i0b * 512 + gcol]));
            float2 q1 = __half22float2(*reinterpret_cast<const __half2*>(&g_PQh[(size_t)i1b * 512 + 256 + gcol]));
            stcs_u32(&g_hh[(size_t)R1 * 256 + gcol],
                     h2u(__floats2half2_rn(acc[mi][j][2] + p1.x + q1.x, acc[mi][j][3] + p1.y + q1.y)));
        }
    }
}

// ---------- K2: crystal stats from fp16 h (sorted segments, MLP=8) ----------
__global__ __launch_bounds__(256) void k_stats(const int* __restrict__ seg) {
    __shared__ int seg_sm[128];
    int tid = threadIdx.x;
    int bi = blockIdx.x;
    if (tid < 128) seg_sm[tid] = seg[bi * 128 + tid];
    __syncthreads();
    int cp = tid & 127, halfsel = tid >> 7;
    int r0 = halfsel * 64;
    size_t rowbase = (size_t)(bi * 128 + r0);
    int cur = seg_sm[r0];
    float s0 = 0.f, s1 = 0.f, q0 = 0.f, q1 = 0.f; int c = 0;
    for (int rb = 0; rb < 64; rb += 8) {
        float2 v[8];
#pragma unroll
        for (int u = 0; u < 8; u++)
            v[u] = u2f2(ldcs_u32(&g_hh[(rowbase + rb + u) * 256 + cp * 2]));
#pragma unroll
        for (int u = 0; u < 8; u++) {
            int sg = seg_sm[r0 + rb + u];
            if (sg != cur) {
                atomicAdd(&g_sum[cur * 256 + cp * 2 + 0], s0);
                atomicAdd(&g_sum[cur * 256 + cp * 2 + 1], s1);
                atomicAdd(&g_sumsq[cur * 256 + cp * 2 + 0], q0);
                atomicAdd(&g_sumsq[cur * 256 + cp * 2 + 1], q1);
                if (cp == 0) atomicAdd(&g_cnt[cur], c);
                s0 = s1 = q0 = q1 = 0.f; c = 0; cur = sg;
            }
            s0 += v[u].x; q0 += v[u].x * v[u].x;
            s1 += v[u].y; q1 += v[u].y * v[u].y;
            c++;
        }
    }
    atomicAdd(&g_sum[cur * 256 + cp * 2 + 0], s0);
    atomicAdd(&g_sum[cur * 256 + cp * 2 + 1], s1);
    atomicAdd(&g_sumsq[cur * 256 + cp * 2 + 0], q0);
    atomicAdd(&g_sumsq[cur * 256 + cp * 2 + 1], q1);
    if (cp == 0) atomicAdd(&g_cnt[cur], c);
}

// ---------- K3: crystal-norm affine coefficients ----------------------------
__global__ void k_finalize(const float* __restrict__ gamma, const float* __restrict__ beta) {
    int c = blockIdx.x, n = threadIdx.x;
    float cnt = fmaxf((float)g_cnt[c], 1.f);
    float mean = g_sum[c * 256 + n] / cnt;
    float var = fmaxf(g_sumsq[c * 256 + n] / cnt - mean * mean, 0.f);
    float a = gamma[n] * rsqrtf(var + EPS);
    g_ca[c * 256 + n] = a;
    g_cb[c * 256 + n] = beta[n] - mean * a;
}

// ---------- K4: per-angle msg + scatter; block-cached ca/cb -----------------
__global__ __launch_bounds__(256) void k_msg(const int* __restrict__ seg,
                                             const int* __restrict__ nidx,
                                             const float* __restrict__ Wm,
                                             const float* __restrict__ lng,
                                             const float* __restrict__ lnb) {
    __shared__ float ca_sm[256], cb_sm[256];
    __shared__ int sg_sm[8];
    int tid = threadIdx.x;
    int lane = tid & 31;
    int w = tid >> 5;
    int row_base = blockIdx.x * 8;
    int row = row_base + w;
    if (tid < 8) sg_sm[tid] = seg[row_base + tid];
    __syncthreads();
    int sg0 = sg_sm[0];
    ca_sm[tid] = g_ca[(size_t)sg0 * 256 + tid];
    cb_sm[tid] = g_cb[(size_t)sg0 * 256 + tid];
    __syncthreads();
    int sg = sg_sm[w];
    const float4* cap = (sg == sg0) ? reinterpret_cast<const float4*>(ca_sm)
                                    : reinterpret_cast<const float4*>(&g_ca[(size_t)sg * 256]);
    const float4* cbp = (sg == sg0) ? reinterpret_cast<const float4*>(cb_sm)
                                    : reinterpret_cast<const float4*>(&g_cb[(size_t)sg * 256]);

    const char* hbase = (const char*)&g_hh[(size_t)row * 256];
    uint2 hcu = ldcs_u64(hbase + lane * 8);
    uint2 hfu = ldcs_u64(hbase + 256 + lane * 8);
    float2 c01 = u2f2(hcu.x), c23 = u2f2(hcu.y);
    float2 f01 = u2f2(hfu.x), f23 = u2f2(hfu.y);
    float4 hc = {c01.x, c01.y, c23.x, c23.y};
    float4 hf = {f01.x, f01.y, f23.x, f23.y};
    float4 ac = cap[lane], af = cap[32 + lane];
    float4 bc = cbp[lane], bf = cbp[32 + lane];
    float4 core, filt;
    core.x = hc.x * ac.x + bc.x; core.y = hc.y * ac.y + bc.y;
    core.z = hc.z * ac.z + bc.z; core.w = hc.w * ac.w + bc.w;
    filt.x = hf.x * af.x + bf.x; filt.y = hf.y * af.y + bf.y;
    filt.z = hf.z * af.z + bf.z; filt.w = hf.w * af.w + bf.w;
    float s1 = core.x + core.y + core.z + core.w;
    float s2 = core.x * core.x + core.y * core.y + core.z * core.z + core.w * core.w;
#pragma unroll
    for (int off = 16; off >= 1; off >>= 1) {
        s1 += __shfl_xor_sync(0xffffffffu, s1, off);
        s2 += __shfl_xor_sync(0xffffffffu, s2, off);
    }
    float mean = s1 * (1.f / 128.f);
    float var = fmaxf(s2 * (1.f / 128.f) - mean * mean, 0.f);
    float rstd = rsqrtf(var + EPS);
    float4 g4 = reinterpret_cast<const float4*>(lng)[lane];
    float4 b4 = reinterpret_cast<const float4*>(lnb)[lane];
    float4 sl;
    sl.x = silu_f((core.x - mean) * rstd * g4.x + b4.x);
    sl.y = silu_f((core.y - mean) * rstd * g4.y + b4.y);
    sl.z = silu_f((core.z - mean) * rstd * g4.z + b4.z);
    sl.w = silu_f((core.w - mean) * rstd * g4.w + b4.w);
    float4 wm = reinterpret_cast<const float4*>(Wm)[lane];
    float gp = filt.x * wm.x + filt.y * wm.y + filt.z * wm.z + filt.w * wm.w;
#pragma unroll
    for (int off = 16; off >= 1; off >>= 1) gp += __shfl_xor_sync(0xffffffffu, gp, off);
    float gate = 1.f / (1.f + __expf(-gp));
    float4 msg = {gate * sl.x, gate * sl.y, gate * sl.z, gate * sl.w};
    int src = nidx[row * 2];
    float* dst = &g_s[(size_t)src * 128 + lane * 4];
    asm volatile("red.global.add.v4.f32 [%0], {%1,%2,%3,%4};"
                 :: "l"(dst), "f"(msg.x), "f"(msg.y), "f"(msg.z), "f"(msg.w) : "memory");
    if (lane == 0) atomicAdd(&g_ecnt[src], 1);
}

// ---------- K5: per-edge LN2 + two residual MLPs, tf32 tensor cores ---------
__global__ __launch_bounds__(512) void k_edge(const float* __restrict__ nbr,
                       const float* __restrict__ ln2g, const float* __restrict__ ln2b,
                       const float* __restrict__ W1a, const float* __restrict__ b1a,
                       const float* __restrict__ W2a, const float* __restrict__ b2a,
                       const float* __restrict__ W1b, const float* __restrict__ b1b,
                       const float* __restrict__ W2b, const float* __restrict__ b2b,
                       float* __restrict__ out) {
    extern __shared__ uint usm[];
    uint* W1AF = usm;
    uint* W2AF = usm + 8192;
    uint* W1BF = usm + 16384;
    uint* W2BF = usm + 24576;
    uint* XF   = usm + 32768;
    uint* H1F  = usm + 36864;
    float* x_sm = (float*)(usm + 38912);
    float* bias = (float*)(usm + 43008);
    float* b1as = bias;
    float* b2as = bias + 64;
    float* b1bs = bias + 192;
    float* b2bs = bias + 256;
    float* g2s  = bias + 384;
    float* bb2s = bias + 512;

    int tid = threadIdx.x;
    int wid = tid >> 5, lane = tid & 31;
    int r = lane >> 2, cq = lane & 3;

    for (int i = tid; i < 8192; i += 512) {
        int j = i >> 7, d = i & 127;
        stage_b_g(W1AF, 16, j, d, W1a[i]);
        stage_b_g(W1BF, 16, j, d, W1b[i]);
        int d2 = i >> 6, j2 = i & 63;
        stage_b_g(W2AF, 8, d2, j2, W2a[i]);
        stage_b_g(W2BF, 8, d2, j2, W2b[i]);
    }
    if (tid < 64) { b1as[tid] = b1a[tid]; bias[192 + tid] = b1b[tid]; }
    else if (tid >= 128 && tid < 256) {
        int t = tid - 128;
        b2as[t] = b2a[t]; b2bs[t] = b2b[t]; g2s[t] = ln2g[t]; bb2s[t] = ln2b[t];
    }
    __syncthreads();

    int mt = wid >> 3;
    int ntw = wid & 7;

    for (int grp = blockIdx.x; grp < N_EDGES / 32; grp += gridDim.x) {
        int e_base = grp * 32;
        {
            int eL = tid >> 4, l16 = tid & 15;
            int e = e_base + eL;
            float inv = 1.f / fmaxf((float)g_ecnt[e], 1.f);
            float4 v0 = ldcs_f4(&g_s[(size_t)e * 128 + l16 * 8]);
            float4 v1 = ldcs_f4(&g_s[(size_t)e * 128 + l16 * 8 + 4]);
            float vals[8] = {v0.x * inv, v0.y * inv, v0.z * inv, v0.w * inv,
                             v1.x * inv, v1.y * inv, v1.z * inv, v1.w * inv};
            float s1 = 0.f, s2 = 0.f;
#pragma unroll
            for (int k = 0; k < 8; k++) { s1 += vals[k]; s2 += vals[k] * vals[k]; }
#pragma unroll
            for (int off = 8; off >= 1; off >>= 1) {
                s1 += __shfl_xor_sync(0xffffffffu, s1, off);
                s2 += __shfl_xor_sync(0xffffffffu, s2, off);
            }
            float mean = s1 * (1.f / 128.f);
            float var = fmaxf(s2 * (1.f / 128.f) - mean * mean, 0.f);
            float rstd = rsqrtf(var + EPS);
            int d0 = l16 * 8;
#pragma unroll
            for (int k = 0; k < 8; k++) {
                float xv = (vals[k] - mean) * rstd * g2s[d0 + k] + bb2s[d0 + k];
                x_sm[eL * 128 + d0 + k] = xv;
                stage_a_g(XF, 16, eL, d0 + k, xv);
            }
        }
        __syncthreads();
        {
            float c[4] = {0.f, 0.f, 0.f, 0.f};
#pragma unroll
            for (int kt = 0; kt < 16; kt++) {
                uint4 au = *reinterpret_cast<uint4*>(&XF[((mt * 16 + kt) * 32 + lane) * 4]);
                uint a[4] = {au.x, au.y, au.z, au.w};
                uint2 bu = *reinterpret_cast<uint2*>(&W1AF[((ntw * 16 + kt) * 32 + lane) * 2]);
                uint b[2] = {bu.x, bu.y};
                mma_tf32(c, a, b);
            }
            int col = ntw * 8 + cq * 2;
            int row0 = mt * 16 + r, row1 = row0 + 8;
            stage_a_g(H1F, 8, row0, col,     silu_f(c[0] + b1as[col]));
            stage_a_g(H1F, 8, row0, col + 1, silu_f(c[1] + b1as[col + 1]));
            stage_a_g(H1F, 8, row1, col,     silu_f(c[2] + b1as[col]));
            stage_a_g(H1F, 8, row1, col + 1, silu_f(c[3] + b1as[col + 1]));
        }
        __syncthreads();
        {
#pragma unroll
            for (int t = 0; t < 2; t++) {
                int nt2 = ntw + t * 8;
                float c[4] = {0.f, 0.f, 0.f, 0.f};
#pragma unroll
                for (int kt = 0; kt < 8; kt++) {
                    uint4 au = *reinterpret_cast<uint4*>(&H1F[((mt * 8 + kt) * 32 + lane) * 4]);
                    uint a[4] = {au.x, au.y, au.z, au.w};
                    uint2 bu = *reinterpret_cast<uint2*>(&W2AF[((nt2 * 8 + kt) * 32 + lane) * 2]);
                    uint b[2] = {bu.x, bu.y};
                    mma_tf32(c, a, b);
                }
                int col = nt2 * 8 + cq * 2;
                int row0 = mt * 16 + r, row1 = row0 + 8;
                float n00 = x_sm[row0 * 128 + col]     + c[0] + b2as[col];
                float n01 = x_sm[row0 * 128 + col + 1] + c[1] + b2as[col + 1];
                float n10 = x_sm[row1 * 128 + col]     + c[2] + b2as[col];
                float n11 = x_sm[row1 * 128 + col + 1] + c[3] + b2as[col + 1];
                x_sm[row0 * 128 + col] = n00;     x_sm[row0 * 128 + col + 1] = n01;
                x_sm[row1 * 128 + col] = n10;     x_sm[row1 * 128 + col + 1] = n11;
                stage_a_g(XF, 16, row0, col, n00); stage_a_g(XF, 16, row0, col + 1, n01);
                stage_a_g(XF, 16, row1, col, n10); stage_a_g(XF, 16, row1, col + 1, n11);
            }
        }
        __syncthreads();
        {
            float c[4] = {0.f, 0.f, 0.f, 0.f};
#pragma unroll
            for (int kt = 0; kt < 16; kt++) {
                uint4 au = *reinterpret_cast<uint4*>(&XF[((mt * 16 + kt) * 32 + lane) * 4]);
                uint a[4] = {au.x, au.y, au.z, au.w};
                uint2 bu = *reinterpret_cast<uint2*>(&W1BF[((ntw * 16 + kt) * 32 + lane) * 2]);
                uint b[2] = {bu.x, bu.y};
                mma_tf32(c, a, b);
            }
            int col = ntw * 8 + cq * 2;
            int row0 = mt * 16 + r, row1 = row0 + 8;
            stage_a_g(H1F, 8, row0, col,     silu_f(c[0] + bias[192 + col]));
            stage_a_g(H1F, 8, row0, col + 1, silu_f(c[1] + bias[192 + col + 1]));
            stage_a_g(H1F, 8, row1, col,     silu_f(c[2] + bias[192 + col]));
            stage_a_g(H1F, 8, row1, col + 1, silu_f(c[3] + bias[192 + col + 1]));
        }
        __syncthreads();
        {
#pragma unroll
            for (int t = 0; t < 2; t++) {
                int nt2 = ntw + t * 8;
                float c[4] = {0.f, 0.f, 0.f, 0.f};
#pragma unroll
                for (int kt = 0; kt < 8; kt++) {
                    uint4 au = *reinterpret_cast<uint4*>(&H1F[((mt * 8 + kt) * 32 + lane) * 4]);
                    uint a[4] = {au.x, au.y, au.z, au.w};
                    uint2 bu = *reinterpret_cast<uint2*>(&W2BF[((nt2 * 8 + kt) * 32 + lane) * 2]);
                    uint b[2] = {bu.x, bu.y};
                    mma_tf32(c, a, b);
                }
                int col = nt2 * 8 + cq * 2;
                int row0 = mt * 16 + r, row1 = row0 + 8;
                int e0 = e_base + row0, e1 = e_base + row1;
                float f00 = x_sm[row0 * 128 + col]     + c[0] + b2bs[col];
                float f01 = x_sm[row0 * 128 + col + 1] + c[1] + b2bs[col + 1];
                float f10 = x_sm[row1 * 128 + col]     + c[2] + b2bs[col];
                float f11 = x_sm[row1 * 128 + col + 1] + c[3] + b2bs[col + 1];
                float2 nb0 = ldcs_f2(&nbr[(size_t)e0 * 128 + col]);
                float2 nb1 = ldcs_f2(&nbr[(size_t)e1 * 128 + col]);
                float2 o0 = {INV_SQRT_2 * (nb0.x + f00), INV_SQRT_2 * (nb0.y + f01)};
                float2 o1 = {INV_SQRT_2 * (nb1.x + f10), INV_SQRT_2 * (nb1.y + f11)};
                stcs_f2(&out[(size_t)e0 * 128 + col], o0);
                stcs_f2(&out[(size_t)e1 * 128 + col], o1);
            }
        }
        __syncthreads();
    }
}

// ---------- launch ----------------------------------------------------------
extern "C" void kernel_launch(void* const* d_in, const int* in_sizes, int n_in,
                              void* d_out, int out_size) {
    const float* nbr_fea   = (const float*)d_in[0];
    const float* angle_fea = (const float*)d_in[1];
    const int*   nidx      = (const int*)d_in[2];
    const int*   cai       = (const int*)d_in[4];
    const float* W_full    = (const float*)d_in[5];
    const float* W_mask    = (const float*)d_in[6];
    const float* cn_gamma  = (const float*)d_in[7];
    const float* cn_beta   = (const float*)d_in[8];
    const float* ln_core_g = (const float*)d_in[9];
    const float* ln_core_b = (const float*)d_in[10];
    const float* ln2_g     = (const float*)d_in[11];
    const float* ln2_b     = (const float*)d_in[12];
    const float* res_W1a   = (const float*)d_in[13];
    const float* res_b1a   = (const float*)d_in[14];
    const float* res_W2a   = (const float*)d_in[15];
    const float* res_b2a   = (const float*)d_in[16];
    const float* res_W1b   = (const float*)d_in[17];
    const float* res_b1b   = (const float*)d_in[18];
    const float* res_W2b   = (const float*)d_in[19];
    const float* res_b2b   = (const float*)d_in[20];
    float* out = (float*)d_out;

    static bool attr_set = false;
    if (!attr_set) {
        cudaFuncSetAttribute(k_edge, cudaFuncAttributeMaxDynamicSharedMemorySize, 176 * 1024);
        cudaFuncSetAttribute(k_gemm_angle, cudaFuncAttributeMaxDynamicSharedMemorySize, 68 * 1024);
        attr_set = true;
    }

    k_zero<<<1024, 256>>>();
    k_gemm_pq<<<dim3((N_EDGES + 127) / 128, 4), 256>>>(nbr_fea, W_full);
    k_gemm_angle<<<dim3(N_ANGLES / 128, 2), 256, 65536>>>(angle_fea, W_full, nidx);
    k_stats<<<N_ANGLES / 128, 256>>>(cai);
    k_finalize<<<N_CRYST, 256>>>(cn_gamma, cn_beta);
    k_msg<<<N_ANGLES / 8, 256>>>(cai, nidx, W_mask, ln_core_g, ln_core_b);
    k_edge<<<148, 512, 43648 * sizeof(float)>>>(nbr_fea, ln2_g, ln2_b,
                                                res_W1a, res_b1a, res_W2a, res_b2a,
                                                res_W1b, res_b1b, res_W2b, res_b2b, out);
}

// round 11
// speedup vs baseline: 2.3796x; 1.0191x over previous
#include <cuda_runtime.h>
#include <cuda_fp16.h>
#include <cstdint>

#define N_EDGES 100000
#define N_ANGLES 400000
#define N_CRYST 512
#define EPS 1e-5f
#define INV_SQRT_2 0.70710678118654752440f

typedef unsigned long long ull;
typedef unsigned int uint;

// ---------- scratch (static device globals; no runtime allocation) ----------
__device__ __half g_PQh[(size_t)N_EDGES * 512];   // P | Q  (fp16 storage)
__device__ __half g_hh[(size_t)N_ANGLES * 256];   // h      (fp16 storage)
__device__ float g_sum[N_CRYST * 256];
__device__ float g_sumsq[N_CRYST * 256];
__device__ int   g_cnt[N_CRYST];
__device__ float g_ca[N_CRYST * 256];
__device__ float g_cb[N_CRYST * 256];
__device__ float g_s[(size_t)N_EDGES * 128];
__device__ int   g_ecnt[N_EDGES];

__device__ __forceinline__ float silu_f(float x) { return x / (1.f + __expf(-x)); }
__device__ __forceinline__ uint tf32u(float x) {
    uint u; asm("cvt.rna.tf32.f32 %0, %1;" : "=r"(u) : "f"(x)); return u;
}
__device__ __forceinline__ void mma_tf32(float d[4], const uint a[4], const uint b[2]) {
    asm volatile(
        "mma.sync.aligned.m16n8k8.row.col.f32.tf32.tf32.f32 "
        "{%0,%1,%2,%3},{%4,%5,%6,%7},{%8,%9},{%0,%1,%2,%3};"
        : "+f"(d[0]), "+f"(d[1]), "+f"(d[2]), "+f"(d[3])
        : "r"(a[0]), "r"(a[1]), "r"(a[2]), "r"(a[3]), "r"(b[0]), "r"(b[1]));
}
__device__ __forceinline__ uint ldcs_u32(const void* p) {
    uint v; asm volatile("ld.global.cs.b32 %0, [%1];" : "=r"(v) : "l"(p)); return v;
}
__device__ __forceinline__ uint2 ldcs_u64(const void* p) {
    uint2 v; asm volatile("ld.global.cs.v2.u32 {%0,%1}, [%2];" : "=r"(v.x), "=r"(v.y) : "l"(p)); return v;
}
__device__ __forceinline__ float2 ldcs_f2(const void* p) {
    float2 v; asm volatile("ld.global.cs.v2.f32 {%0,%1}, [%2];" : "=f"(v.x), "=f"(v.y) : "l"(p)); return v;
}
__device__ __forceinline__ float4 ldcs_f4(const void* p) {
    float4 v; asm volatile("ld.global.cs.v4.f32 {%0,%1,%2,%3}, [%4];"
        : "=f"(v.x), "=f"(v.y), "=f"(v.z), "=f"(v.w) : "l"(p)); return v;
}
__device__ __forceinline__ void stcs_u32(void* p, uint v) {
    asm volatile("st.global.cs.b32 [%0], %1;" :: "l"(p), "r"(v) : "memory");
}
__device__ __forceinline__ void stcs_f2(void* p, float2 v) {
    asm volatile("st.global.cs.v2.f32 [%0], {%1,%2};" :: "l"(p), "f"(v.x), "f"(v.y) : "memory");
}
__device__ __forceinline__ uint h2u(__half2 h) { return *reinterpret_cast<uint*>(&h); }
__device__ __forceinline__ float2 u2f2(uint u) {
    __half2 h = *reinterpret_cast<__half2*>(&u); return __half22float2(h);
}

// ---- fragment-major staging helpers ----------------------------------------
__device__ __forceinline__ void stage_a_g(uint* buf, int KT, int row, int C, float v) {
    int mt = row >> 4, r = row & 15, kt = C >> 3, c = C & 7;
    int lane = (r & 7) * 4 + (c & 3);
    int slot = (r >> 3) + 2 * (c >> 2);
    buf[((mt * KT + kt) * 32 + lane) * 4 + slot] = tf32u(v);
}
__device__ __forceinline__ void stage_b_g(uint* buf, int KT, int nrow, int C, float v) {
    int nt = nrow >> 3, n = nrow & 7, kt = C >> 3, c = C & 7;
    int lane = n * 4 + (c & 3);
    int slot = c >> 2;
    buf[((nt * KT + kt) * 32 + lane) * 2 + slot] = tf32u(v);
}

// ============ tf32 MMA GEMM: BM=128, BN=128, BK=32, 256 thr (8 warps 4x2) ===
struct MmaSmem { uint a[128 * 32]; uint b[128 * 32]; };

__device__ __forceinline__ void mma_chunk(MmaSmem& sm, int wm, int wn, int lane,
                                          float acc[2][8][4]) {
#pragma unroll
    for (int kt = 0; kt < 4; kt++) {
        uint4 a0u = *reinterpret_cast<uint4*>(&sm.a[(((wm * 2 + 0) * 4 + kt) * 32 + lane) * 4]);
        uint4 a1u = *reinterpret_cast<uint4*>(&sm.a[(((wm * 2 + 1) * 4 + kt) * 32 + lane) * 4]);
        uint a0[4] = {a0u.x, a0u.y, a0u.z, a0u.w};
        uint a1[4] = {a1u.x, a1u.y, a1u.z, a1u.w};
#pragma unroll
        for (int j = 0; j < 8; j++) {
            uint2 bu = *reinterpret_cast<uint2*>(&sm.b[(((wn * 8 + j) * 4 + kt) * 32 + lane) * 2]);
            uint b[2] = {bu.x, bu.y};
            mma_tf32(acc[0][j], a0, b);
            mma_tf32(acc[1][j], a1, b);
        }
    }
}

// ---------- K1a: P/Q GEMM + (folded) scratch zeroing ------------------------
// Zeroing of g_s/g_ecnt/g_sum/g_sumsq/g_cnt is grid-strided across this
// kernel's 3128 blocks; consumers (k_stats/k_msg/k_edge) launch strictly later.
__global__ __launch_bounds__(256) void k_gemm_pq(const float* __restrict__ nbr,
                                                 const float* __restrict__ W) {
    // folded zeroing (independent of GEMM work; no sync needed here)
    {
        size_t nblk = (size_t)gridDim.x * gridDim.y;
        size_t bidl = (size_t)blockIdx.y * gridDim.x + blockIdx.x;
        size_t i = bidl * 256 + threadIdx.x;
        size_t stride = nblk * 256;
        float4 z4 = {0.f, 0.f, 0.f, 0.f};
        for (size_t t = i; t < (size_t)N_EDGES * 32; t += stride)
            *reinterpret_cast<float4*>(&g_s[t * 4]) = z4;
        for (size_t t = i; t < (size_t)N_EDGES; t += stride) g_ecnt[t] = 0;
        for (size_t t = i; t < (size_t)N_CRYST * 256; t += stride) { g_sum[t] = 0.f; g_sumsq[t] = 0.f; }
        for (size_t t = i; t < (size_t)N_CRYST; t += stride) g_cnt[t] = 0;
    }

    __shared__ MmaSmem sm;
    int tid = threadIdx.x;
    int warp = tid >> 5, lane = tid & 31;
    int wm = warp >> 1, wn = warp & 1;
    int m_base = blockIdx.x * 128;
    int nb = blockIdx.y & 1, qsel = blockIdx.y >> 1;
    int koff = 64 + qsel * 128;
    int n_base = nb * 128;

    float acc[2][8][4];
#pragma unroll
    for (int i = 0; i < 2; i++)
#pragma unroll
        for (int j = 0; j < 8; j++)
#pragma unroll
            for (int k = 0; k < 4; k++) acc[i][j][k] = 0.f;

    for (int kc = 0; kc < 4; kc++) {
        int k0 = kc * 32;
#pragma unroll
        for (int it = 0; it < 4; it++) {
            int lin = it * 256 + tid;
            int row = lin >> 3, c4 = (lin & 7) * 4;
            int grow = m_base + row; if (grow >= N_EDGES) grow = N_EDGES - 1;
            float4 v = *reinterpret_cast<const float4*>(nbr + (size_t)grow * 128 + k0 + c4);
            stage_a_g(sm.a, 4, row, c4 + 0, v.x);
            stage_a_g(sm.a, 4, row, c4 + 1, v.y);
            stage_a_g(sm.a, 4, row, c4 + 2, v.z);
            stage_a_g(sm.a, 4, row, c4 + 3, v.w);
        }
#pragma unroll
        for (int it = 0; it < 4; it++) {
            int lin = it * 256 + tid;
            int row = lin >> 3, c4 = (lin & 7) * 4;
            float4 v = *reinterpret_cast<const float4*>(W + (size_t)(n_base + row) * 320 + koff + k0 + c4);
            stage_b_g(sm.b, 4, row, c4 + 0, v.x);
            stage_b_g(sm.b, 4, row, c4 + 1, v.y);
            stage_b_g(sm.b, 4, row, c4 + 2, v.z);
            stage_b_g(sm.b, 4, row, c4 + 3, v.w);
        }
        __syncthreads();
        mma_chunk(sm, wm, wn, lane, acc);
        __syncthreads();
    }
    int r = lane >> 2, cq = lane & 3;
#pragma unroll
    for (int mi = 0; mi < 2; mi++) {
        int R0 = m_base + wm * 32 + mi * 16 + r;
        int R1 = R0 + 8;
#pragma unroll
        for (int j = 0; j < 8; j++) {
            int gcol = qsel * 256 + n_base + wn * 64 + j * 8 + cq * 2;
            if (R0 < N_EDGES)
                *reinterpret_cast<__half2*>(&g_PQh[(size_t)R0 * 512 + gcol]) =
                    __floats2half2_rn(acc[mi][j][0], acc[mi][j][1]);
            if (R1 < N_EDGES)
                *reinterpret_cast<__half2*>(&g_PQh[(size_t)R1 * 512 + gcol]) =
                    __floats2half2_rn(acc[mi][j][2], acc[mi][j][3]);
        }
    }
}

// ---------- K1b: h = angle@Wa.T + P[i0] + Q[i1] (single-stage, K=64) --------
__global__ __launch_bounds__(256) void k_gemm_angle(const float* __restrict__ ang,
                                                    const float* __restrict__ W,
                                                    const int* __restrict__ nidx) {
    extern __shared__ uint dsm[];
    uint* AF = dsm;            // KT=8, 8 m-tiles
    uint* BF = dsm + 8192;     // KT=8, 16 n-tiles
    __shared__ int i0_sm[128], i1_sm[128];
    int tid = threadIdx.x;
    int warp = tid >> 5, lane = tid & 31;
    int wm = warp >> 1, wn = warp & 1;
    int m_base = blockIdx.x * 128;
    int n_base = blockIdx.y * 128;

    if (tid < 128) {
        i0_sm[tid] = nidx[(m_base + tid) * 2 + 0];
        i1_sm[tid] = nidx[(m_base + tid) * 2 + 1];
    }

#pragma unroll
    for (int it = 0; it < 8; it++) {
        int lin = it * 256 + tid;
        int row = lin >> 4, c4 = (lin & 15) * 4;
        float4 v = ldcs_f4(ang + (size_t)(m_base + row) * 64 + c4);
        stage_a_g(AF, 8, row, c4 + 0, v.x);
        stage_a_g(AF, 8, row, c4 + 1, v.y);
        stage_a_g(AF, 8, row, c4 + 2, v.z);
        stage_a_g(AF, 8, row, c4 + 3, v.w);
    }
#pragma unroll
    for (int it = 0; it < 8; it++) {
        int lin = it * 256 + tid;
        int row = lin >> 4, c4 = (lin & 15) * 4;
        float4 v = *reinterpret_cast<const float4*>(W + (size_t)(n_base + row) * 320 + c4);
        stage_b_g(BF, 8, row, c4 + 0, v.x);
        stage_b_g(BF, 8, row, c4 + 1, v.y);
        stage_b_g(BF, 8, row, c4 + 2, v.z);
        stage_b_g(BF, 8, row, c4 + 3, v.w);
    }
    __syncthreads();

    float acc[2][8][4];
#pragma unroll
    for (int i = 0; i < 2; i++)
#pragma unroll
        for (int j = 0; j < 8; j++)
#pragma unroll
            for (int k = 0; k < 4; k++) acc[i][j][k] = 0.f;

#pragma unroll
    for (int kt = 0; kt < 8; kt++) {
        uint4 a0u = *reinterpret_cast<uint4*>(&AF[(((wm * 2 + 0) * 8 + kt) * 32 + lane) * 4]);
        uint4 a1u = *reinterpret_cast<uint4*>(&AF[(((wm * 2 + 1) * 8 + kt) * 32 + lane) * 4]);
        uint a0[4] = {a0u.x, a0u.y, a0u.z, a0u.w};
        uint a1[4] = {a1u.x, a1u.y, a1u.z, a1u.w};
#pragma unroll
        for (int j = 0; j < 8; j++) {
            uint2 bu = *reinterpret_cast<uint2*>(&BF[(((wn * 8 + j) * 8 + kt) * 32 + lane) * 2]);
            uint b[2] = {bu.x, bu.y};
            mma_tf32(acc[0][j], a0, b);
            mma_tf32(acc[1][j], a1, b);
        }
    }

    int r = lane >> 2, cq = lane & 3;
#pragma unroll
    for (int mi = 0; mi < 2; mi++) {
        int lr0 = wm * 32 + mi * 16 + r;
        int lr1 = lr0 + 8;
        int R0 = m_base + lr0, R1 = m_base + lr1;
        int i0a = i0_sm[lr0], i1a = i1_sm[lr0];
        int i0b = i0_sm[lr1], i1b = i1_sm[lr1];
#pragma unroll
        for (int j = 0; j < 8; j++) {
            int gcol = n_base + wn * 64 + j * 8 + cq * 2;
            float2 p0 = __half22float2(*reinterpret_cast<const __half2*>(&g_PQh[(size_t)i0a * 512 + gcol]));
            float2 q0 = __half22float2(*reinterpret_cast<const __half2*>(&g_PQh[(size_t)i1a * 512 + 256 + gcol]));
            stcs_u32(&g_hh[(size_t)R0 * 256 + gcol],
                     h2u(__floats2half2_rn(acc[mi][j][0] + p0.x + q0.x, acc[mi][j][1] + p0.y + q0.y)));
            float2 p1 = __half22float2(*reinterpret_cast<const __half2*>(&g_PQh[(size_t)i0b * 512 + gcol]));
            float2 q1 = __half22float2(*reinterpret_cast<const __half2*>(&g_PQh[(size_t)i1b * 512 + 256 + gcol]));
            stcs_u32(&g_hh[(size_t)R1 * 256 + gcol],
                     h2u(__floats2half2_rn(acc[mi][j][2] + p1.x + q1.x, acc[mi][j][3] + p1.y + q1.y)));
        }
    }
}

// ---------- K2: crystal stats from fp16 h (sorted segments, MLP=8) ----------
__global__ __launch_bounds__(256) void k_stats(const int* __restrict__ seg) {
    __shared__ int seg_sm[128];
    int tid = threadIdx.x;
    int bi = blockIdx.x;
    if (tid < 128) seg_sm[tid] = seg[bi * 128 + tid];
    __syncthreads();
    int cp = tid & 127, halfsel = tid >> 7;
    int r0 = halfsel * 64;
    size_t rowbase = (size_t)(bi * 128 + r0);
    int cur = seg_sm[r0];
    float s0 = 0.f, s1 = 0.f, q0 = 0.f, q1 = 0.f; int c = 0;
    for (int rb = 0; rb < 64; rb += 8) {
        float2 v[8];
#pragma unroll
        for (int u = 0; u < 8; u++)
            v[u] = u2f2(ldcs_u32(&g_hh[(rowbase + rb + u) * 256 + cp * 2]));
#pragma unroll
        for (int u = 0; u < 8; u++) {
            int sg = seg_sm[r0 + rb + u];
            if (sg != cur) {
                atomicAdd(&g_sum[cur * 256 + cp * 2 + 0], s0);
                atomicAdd(&g_sum[cur * 256 + cp * 2 + 1], s1);
                atomicAdd(&g_sumsq[cur * 256 + cp * 2 + 0], q0);
                atomicAdd(&g_sumsq[cur * 256 + cp * 2 + 1], q1);
                if (cp == 0) atomicAdd(&g_cnt[cur], c);
                s0 = s1 = q0 = q1 = 0.f; c = 0; cur = sg;
            }
            s0 += v[u].x; q0 += v[u].x * v[u].x;
            s1 += v[u].y; q1 += v[u].y * v[u].y;
            c++;
        }
    }
    atomicAdd(&g_sum[cur * 256 + cp * 2 + 0], s0);
    atomicAdd(&g_sum[cur * 256 + cp * 2 + 1], s1);
    atomicAdd(&g_sumsq[cur * 256 + cp * 2 + 0], q0);
    atomicAdd(&g_sumsq[cur * 256 + cp * 2 + 1], q1);
    if (cp == 0) atomicAdd(&g_cnt[cur], c);
}

// ---------- K3: crystal-norm affine coefficients ----------------------------
__global__ void k_finalize(const float* __restrict__ gamma, const float* __restrict__ beta) {
    int c = blockIdx.x, n = threadIdx.x;
    float cnt = fmaxf((float)g_cnt[c], 1.f);
    float mean = g_sum[c * 256 + n] / cnt;
    float var = fmaxf(g_sumsq[c * 256 + n] / cnt - mean * mean, 0.f);
    float a = gamma[n] * rsqrtf(var + EPS);
    g_ca[c * 256 + n] = a;
    g_cb[c * 256 + n] = beta[n] - mean * a;
}

// ---------- K4: per-angle msg + scatter into edge sums (1 warp/angle) -------
__global__ __launch_bounds__(256) void k_msg(const int* __restrict__ seg,
                                             const int* __restrict__ nidx,
                                             const float* __restrict__ Wm,
                                             const float* __restrict__ lng,
                                             const float* __restrict__ lnb) {
    int lane = threadIdx.x & 31;
    int row = blockIdx.x * 8 + (threadIdx.x >> 5);
    const char* hbase = (const char*)&g_hh[(size_t)row * 256];
    uint2 hcu = ldcs_u64(hbase + lane * 8);
    uint2 hfu = ldcs_u64(hbase + 256 + lane * 8);
    float2 c01 = u2f2(hcu.x), c23 = u2f2(hcu.y);
    float2 f01 = u2f2(hfu.x), f23 = u2f2(hfu.y);
    float4 hc = {c01.x, c01.y, c23.x, c23.y};
    float4 hf = {f01.x, f01.y, f23.x, f23.y};
    int sg = seg[row];
    const float4* ca = reinterpret_cast<const float4*>(&g_ca[(size_t)sg * 256]);
    const float4* cb = reinterpret_cast<const float4*>(&g_cb[(size_t)sg * 256]);
    float4 ac = ca[lane], af = ca[32 + lane];
    float4 bc = cb[lane], bf = cb[32 + lane];
    float4 core, filt;
    core.x = hc.x * ac.x + bc.x; core.y = hc.y * ac.y + bc.y;
    core.z = hc.z * ac.z + bc.z; core.w = hc.w * ac.w + bc.w;
    filt.x = hf.x * af.x + bf.x; filt.y = hf.y * af.y + bf.y;
    filt.z = hf.z * af.z + bf.z; filt.w = hf.w * af.w + bf.w;
    float s1 = core.x + core.y + core.z + core.w;
    float s2 = core.x * core.x + core.y * core.y + core.z * core.z + core.w * core.w;
#pragma unroll
    for (int off = 16; off >= 1; off >>= 1) {
        s1 += __shfl_xor_sync(0xffffffffu, s1, off);
        s2 += __shfl_xor_sync(0xffffffffu, s2, off);
    }
    float mean = s1 * (1.f / 128.f);
    float var = fmaxf(s2 * (1.f / 128.f) - mean * mean, 0.f);
    float rstd = rsqrtf(var + EPS);
    float4 g4 = reinterpret_cast<const float4*>(lng)[lane];
    float4 b4 = reinterpret_cast<const float4*>(lnb)[lane];
    float4 sl;
    sl.x = silu_f((core.x - mean) * rstd * g4.x + b4.x);
    sl.y = silu_f((core.y - mean) * rstd * g4.y + b4.y);
    sl.z = silu_f((core.z - mean) * rstd * g4.z + b4.z);
    sl.w = silu_f((core.w - mean) * rstd * g4.w + b4.w);
    float4 wm = reinterpret_cast<const float4*>(Wm)[lane];
    float gp = filt.x * wm.x + filt.y * wm.y + filt.z * wm.z + filt.w * wm.w;
#pragma unroll
    for (int off = 16; off >= 1; off >>= 1) gp += __shfl_xor_sync(0xffffffffu, gp, off);
    float gate = 1.f / (1.f + __expf(-gp));
    float4 msg = {gate * sl.x, gate * sl.y, gate * sl.z, gate * sl.w};
    int src = nidx[row * 2];
    float* dst = &g_s[(size_t)src * 128 + lane * 4];
    asm volatile("red.global.add.v4.f32 [%0], {%1,%2,%3,%4};"
                 :: "l"(dst), "f"(msg.x), "f"(msg.y), "f"(msg.z), "f"(msg.w) : "memory");
    if (lane == 0) atomicAdd(&g_ecnt[src], 1);
}

// ---------- K5: per-edge LN2 + two residual MLPs, tf32 tensor cores ---------
__global__ __launch_bounds__(512) void k_edge(const float* __restrict__ nbr,
                       const float* __restrict__ ln2g, const float* __restrict__ ln2b,
                       const float* __restrict__ W1a, const float* __restrict__ b1a,
                       const float* __restrict__ W2a, const float* __restrict__ b2a,
                       const float* __restrict__ W1b, const float* __restrict__ b1b,
                       const float* __restrict__ W2b, const float* __restrict__ b2b,
                       float* __restrict__ out) {
    extern __shared__ uint usm[];
    uint* W1AF = usm;
    uint* W2AF = usm + 8192;
    uint* W1BF = usm + 16384;
    uint* W2BF = usm + 24576;
    uint* XF   = usm + 32768;
    uint* H1F  = usm + 36864;
    float* x_sm = (float*)(usm + 38912);
    float* bias = (float*)(usm + 43008);
    float* b1as = bias;
    float* b2as = bias + 64;
    float* b1bs = bias + 192;
    float* b2bs = bias + 256;
    float* g2s  = bias + 384;
    float* bb2s = bias + 512;

    int tid = threadIdx.x;
    int wid = tid >> 5, lane = tid & 31;
    int r = lane >> 2, cq = lane & 3;

    for (int i = tid; i < 8192; i += 512) {
        int j = i >> 7, d = i & 127;
        stage_b_g(W1AF, 16, j, d, W1a[i]);
        stage_b_g(W1BF, 16, j, d, W1b[i]);
        int d2 = i >> 6, j2 = i & 63;
        stage_b_g(W2AF, 8, d2, j2, W2a[i]);
        stage_b_g(W2BF, 8, d2, j2, W2b[i]);
    }
    if (tid < 64) { b1as[tid] = b1a[tid]; bias[192 + tid] = b1b[tid]; }
    else if (tid >= 128 && tid < 256) {
        int t = tid - 128;
        b2as[t] = b2a[t]; b2bs[t] = b2b[t]; g2s[t] = ln2g[t]; bb2s[t] = ln2b[t];
    }
    __syncthreads();

    int mt = wid >> 3;
    int ntw = wid & 7;

    for (int grp = blockIdx.x; grp < N_EDGES / 32; grp += gridDim.x) {
        int e_base = grp * 32;
        {
            int eL = tid >> 4, l16 = tid & 15;
            int e = e_base + eL;
            float inv = 1.f / fmaxf((float)g_ecnt[e], 1.f);
            float4 v0 = ldcs_f4(&g_s[(size_t)e * 128 + l16 * 8]);
            float4 v1 = ldcs_f4(&g_s[(size_t)e * 128 + l16 * 8 + 4]);
            float vals[8] = {v0.x * inv, v0.y * inv, v0.z * inv, v0.w * inv,
                             v1.x * inv, v1.y * inv, v1.z * inv, v1.w * inv};
            float s1 = 0.f, s2 = 0.f;
#pragma unroll
            for (int k = 0; k < 8; k++) { s1 += vals[k]; s2 += vals[k] * vals[k]; }
#pragma unroll
            for (int off = 8; off >= 1; off >>= 1) {
                s1 += __shfl_xor_sync(0xffffffffu, s1, off);
                s2 += __shfl_xor_sync(0xffffffffu, s2, off);
            }
            float mean = s1 * (1.f / 128.f);
            float var = fmaxf(s2 * (1.f / 128.f) - mean * mean, 0.f);
            float rstd = rsqrtf(var + EPS);
            int d0 = l16 * 8;
#pragma unroll
            for (int k = 0; k < 8; k++) {
                float xv = (vals[k] - mean) * rstd * g2s[d0 + k] + bb2s[d0 + k];
                x_sm[eL * 128 + d0 + k] = xv;
                stage_a_g(XF, 16, eL, d0 + k, xv);
            }
        }
        __syncthreads();
        {
            float c[4] = {0.f, 0.f, 0.f, 0.f};
#pragma unroll
            for (int kt = 0; kt < 16; kt++) {
                uint4 au = *reinterpret_cast<uint4*>(&XF[((mt * 16 + kt) * 32 + lane) * 4]);
                uint a[4] = {au.x, au.y, au.z, au.w};
                uint2 bu = *reinterpret_cast<uint2*>(&W1AF[((ntw * 16 + kt) * 32 + lane) * 2]);
                uint b[2] = {bu.x, bu.y};
                mma_tf32(c, a, b);
            }
            int col = ntw * 8 + cq * 2;
            int row0 = mt * 16 + r, row1 = row0 + 8;
            stage_a_g(H1F, 8, row0, col,     silu_f(c[0] + b1as[col]));
            stage_a_g(H1F, 8, row0, col + 1, silu_f(c[1] + b1as[col + 1]));
            stage_a_g(H1F, 8, row1, col,     silu_f(c[2] + b1as[col]));
            stage_a_g(H1F, 8, row1, col + 1, silu_f(c[3] + b1as[col + 1]));
        }
        __syncthreads();
        {
#pragma unroll
            for (int t = 0; t < 2; t++) {
                int nt2 = ntw + t * 8;
                float c[4] = {0.f, 0.f, 0.f, 0.f};
#pragma unroll
                for (int kt = 0; kt < 8; kt++) {
                    uint4 au = *reinterpret_cast<uint4*>(&H1F[((mt * 8 + kt) * 32 + lane) * 4]);
                    uint a[4] = {au.x, au.y, au.z, au.w};
                    uint2 bu = *reinterpret_cast<uint2*>(&W2AF[((nt2 * 8 + kt) * 32 + lane) * 2]);
                    uint b[2] = {bu.x, bu.y};
                    mma_tf32(c, a, b);
                }
                int col = nt2 * 8 + cq * 2;
                int row0 = mt * 16 + r, row1 = row0 + 8;
                float n00 = x_sm[row0 * 128 + col]     + c[0] + b2as[col];
                float n01 = x_sm[row0 * 128 + col + 1] + c[1] + b2as[col + 1];
                float n10 = x_sm[row1 * 128 + col]     + c[2] + b2as[col];
                float n11 = x_sm[row1 * 128 + col + 1] + c[3] + b2as[col + 1];
                x_sm[row0 * 128 + col] = n00;     x_sm[row0 * 128 + col + 1] = n01;
                x_sm[row1 * 128 + col] = n10;     x_sm[row1 * 128 + col + 1] = n11;
                stage_a_g(XF, 16, row0, col, n00); stage_a_g(XF, 16, row0, col + 1, n01);
                stage_a_g(XF, 16, row1, col, n10); stage_a_g(XF, 16, row1, col + 1, n11);
            }
        }
        __syncthreads();
        {
            float c[4] = {0.f, 0.f, 0.f, 0.f};
#pragma unroll
            for (int kt = 0; kt < 16; kt++) {
                uint4 au = *reinterpret_cast<uint4*>(&XF[((mt * 16 + kt) * 32 + lane) * 4]);
                uint a[4] = {au.x, au.y, au.z, au.w};
                uint2 bu = *reinterpret_cast<uint2*>(&W1BF[((ntw * 16 + kt) * 32 + lane) * 2]);
                uint b[2] = {bu.x, bu.y};
                mma_tf32(c, a, b);
            }
            int col = ntw * 8 + cq * 2;
            int row0 = mt * 16 + r, row1 = row0 + 8;
            stage_a_g(H1F, 8, row0, col,     silu_f(c[0] + bias[192 + col]));
            stage_a_g(H1F, 8, row0, col + 1, silu_f(c[1] + bias[192 + col + 1]));
            stage_a_g(H1F, 8, row1, col,     silu_f(c[2] + bias[192 + col]));
            stage_a_g(H1F, 8, row1, col + 1, silu_f(c[3] + bias[192 + col + 1]));
        }
        __syncthreads();
        {
#pragma unroll
            for (int t = 0; t < 2; t++) {
                int nt2 = ntw + t * 8;
                float c[4] = {0.f, 0.f, 0.f, 0.f};
#pragma unroll
                for (int kt = 0; kt < 8; kt++) {
                    uint4 au = *reinterpret_cast<uint4*>(&H1F[((mt * 8 + kt) * 32 + lane) * 4]);
                    uint a[4] = {au.x, au.y, au.z, au.w};
                    uint2 bu = *reinterpret_cast<uint2*>(&W2BF[((nt2 * 8 + kt) * 32 + lane) * 2]);
                    uint b[2] = {bu.x, bu.y};
                    mma_tf32(c, a, b);
                }
                int col = nt2 * 8 + cq * 2;
                int row0 = mt * 16 + r, row1 = row0 + 8;
                int e0 = e_base + row0, e1 = e_base + row1;
                float f00 = x_sm[row0 * 128 + col]     + c[0] + b2bs[col];
                float f01 = x_sm[row0 * 128 + col + 1] + c[1] + b2bs[col + 1];
                float f10 = x_sm[row1 * 128 + col]     + c[2] + b2bs[col];
                float f11 = x_sm[row1 * 128 + col + 1] + c[3] + b2bs[col + 1];
                float2 nb0 = ldcs_f2(&nbr[(size_t)e0 * 128 + col]);
                float2 nb1 = ldcs_f2(&nbr[(size_t)e1 * 128 + col]);
                float2 o0 = {INV_SQRT_2 * (nb0.x + f00), INV_SQRT_2 * (nb0.y + f01)};
                float2 o1 = {INV_SQRT_2 * (nb1.x + f10), INV_SQRT_2 * (nb1.y + f11)};
                stcs_f2(&out[(size_t)e0 * 128 + col], o0);
                stcs_f2(&out[(size_t)e1 * 128 + col], o1);
            }
        }
        __syncthreads();
    }
}

// ---------- launch ----------------------------------------------------------
extern "C" void kernel_launch(void* const* d_in, const int* in_sizes, int n_in,
                              void* d_out, int out_size) {
    const float* nbr_fea   = (const float*)d_in[0];
    const float* angle_fea = (const float*)d_in[1];
    const int*   nidx      = (const int*)d_in[2];
    const int*   cai       = (const int*)d_in[4];
    const float* W_full    = (const float*)d_in[5];
    const float* W_mask    = (const float*)d_in[6];
    const float* cn_gamma  = (const float*)d_in[7];
    const float* cn_beta   = (const float*)d_in[8];
    const float* ln_core_g = (const float*)d_in[9];
    const float* ln_core_b = (const float*)d_in[10];
    const float* ln2_g     = (const float*)d_in[11];
    const float* ln2_b     = (const float*)d_in[12];
    const float* res_W1a   = (const float*)d_in[13];
    const float* res_b1a   = (const float*)d_in[14];
    const float* res_W2a   = (const float*)d_in[15];
    const float* res_b2a   = (const float*)d_in[16];
    const float* res_W1b   = (const float*)d_in[17];
    const float* res_b1b   = (const float*)d_in[18];
    const float* res_W2b   = (const float*)d_in[19];
    const float* res_b2b   = (const float*)d_in[20];
    float* out = (float*)d_out;

    static bool attr_set = false;
    if (!attr_set) {
        cudaFuncSetAttribute(k_edge, cudaFuncAttributeMaxDynamicSharedMemorySize, 176 * 1024);
        cudaFuncSetAttribute(k_gemm_angle, cudaFuncAttributeMaxDynamicSharedMemorySize, 68 * 1024);
        attr_set = true;
    }

    k_gemm_pq<<<dim3((N_EDGES + 127) / 128, 4), 256>>>(nbr_fea, W_full);
    k_gemm_angle<<<dim3(N_ANGLES / 128, 2), 256, 65536>>>(angle_fea, W_full, nidx);
    k_stats<<<N_ANGLES / 128, 256>>>(cai);
    k_finalize<<<N_CRYST, 256>>>(cn_gamma, cn_beta);
    k_msg<<<N_ANGLES / 8, 256>>>(cai, nidx, W_mask, ln_core_g, ln_core_b);
    k_edge<<<148, 512, 43648 * sizeof(float)>>>(nbr_fea, ln2_g, ln2_b,
                                                res_W1a, res_b1a, res_W2a, res_b2a,
                                                res_W1b, res_b1b, res_W2b, res_b2b, out);
}

// round 12
// speedup vs baseline: 2.3922x; 1.0053x over previous
#include <cuda_runtime.h>
#include <cuda_fp16.h>
#include <cstdint>

#define N_EDGES 100000
#define N_ANGLES 400000
#define N_CRYST 512
#define EPS 1e-5f
#define INV_SQRT_2 0.70710678118654752440f

typedef unsigned long long ull;
typedef unsigned int uint;

// ---------- scratch (static device globals; no runtime allocation) ----------
__device__ __half g_PQh[(size_t)N_EDGES * 512];   // P | Q  (fp16 storage)
__device__ __half g_hh[(size_t)N_ANGLES * 256];   // h      (fp16 storage)
__device__ float g_sum[N_CRYST * 256];
__device__ float g_sumsq[N_CRYST * 256];
__device__ int   g_cnt[N_CRYST];
__device__ float g_ca[N_CRYST * 256];
__device__ float g_cb[N_CRYST * 256];
__device__ float g_s[(size_t)N_EDGES * 128];
__device__ int   g_ecnt[N_EDGES];

__device__ __forceinline__ float silu_f(float x) { return x / (1.f + __expf(-x)); }
__device__ __forceinline__ uint tf32u(float x) {
    uint u; asm("cvt.rna.tf32.f32 %0, %1;" : "=r"(u) : "f"(x)); return u;
}
__device__ __forceinline__ void mma_tf32(float d[4], const uint a[4], const uint b[2]) {
    asm volatile(
        "mma.sync.aligned.m16n8k8.row.col.f32.tf32.tf32.f32 "
        "{%0,%1,%2,%3},{%4,%5,%6,%7},{%8,%9},{%0,%1,%2,%3};"
        : "+f"(d[0]), "+f"(d[1]), "+f"(d[2]), "+f"(d[3])
        : "r"(a[0]), "r"(a[1]), "r"(a[2]), "r"(a[3]), "r"(b[0]), "r"(b[1]));
}
__device__ __forceinline__ uint ldcs_u32(const void* p) {
    uint v; asm volatile("ld.global.cs.b32 %0, [%1];" : "=r"(v) : "l"(p)); return v;
}
__device__ __forceinline__ uint2 ldcs_u64(const void* p) {
    uint2 v; asm volatile("ld.global.cs.v2.u32 {%0,%1}, [%2];" : "=r"(v.x), "=r"(v.y) : "l"(p)); return v;
}
__device__ __forceinline__ float2 ldcs_f2(const void* p) {
    float2 v; asm volatile("ld.global.cs.v2.f32 {%0,%1}, [%2];" : "=f"(v.x), "=f"(v.y) : "l"(p)); return v;
}
__device__ __forceinline__ float4 ldcs_f4(const void* p) {
    float4 v; asm volatile("ld.global.cs.v4.f32 {%0,%1,%2,%3}, [%4];"
        : "=f"(v.x), "=f"(v.y), "=f"(v.z), "=f"(v.w) : "l"(p)); return v;
}
__device__ __forceinline__ void stcs_u32(void* p, uint v) {
    asm volatile("st.global.cs.b32 [%0], %1;" :: "l"(p), "r"(v) : "memory");
}
__device__ __forceinline__ void stcs_f2(void* p, float2 v) {
    asm volatile("st.global.cs.v2.f32 [%0], {%1,%2};" :: "l"(p), "f"(v.x), "f"(v.y) : "memory");
}
__device__ __forceinline__ uint h2u(__half2 h) { return *reinterpret_cast<uint*>(&h); }
__device__ __forceinline__ float2 u2f2(uint u) {
    __half2 h = *reinterpret_cast<__half2*>(&u); return __half22float2(h);
}

// ---------- K0: zero scratch ----------
__global__ void k_zero() {
    size_t i = (size_t)blockIdx.x * blockDim.x + threadIdx.x;
    size_t stride = (size_t)gridDim.x * blockDim.x;
    float4 z4 = {0.f, 0.f, 0.f, 0.f};
    for (size_t t = i; t < (size_t)N_EDGES * 32; t += stride)
        *reinterpret_cast<float4*>(&g_s[t * 4]) = z4;
    for (size_t t = i; t < (size_t)N_EDGES; t += stride) g_ecnt[t] = 0;
    for (size_t t = i; t < (size_t)N_CRYST * 256; t += stride) { g_sum[t] = 0.f; g_sumsq[t] = 0.f; }
    for (size_t t = i; t < (size_t)N_CRYST; t += stride) g_cnt[t] = 0;
}

// ---- fragment-major staging helpers ----------------------------------------
__device__ __forceinline__ void stage_a_g(uint* buf, int KT, int row, int C, float v) {
    int mt = row >> 4, r = row & 15, kt = C >> 3, c = C & 7;
    int lane = (r & 7) * 4 + (c & 3);
    int slot = (r >> 3) + 2 * (c >> 2);
    buf[((mt * KT + kt) * 32 + lane) * 4 + slot] = tf32u(v);
}
__device__ __forceinline__ void stage_b_g(uint* buf, int KT, int nrow, int C, float v) {
    int nt = nrow >> 3, n = nrow & 7, kt = C >> 3, c = C & 7;
    int lane = n * 4 + (c & 3);
    int slot = c >> 2;
    buf[((nt * KT + kt) * 32 + lane) * 2 + slot] = tf32u(v);
}

// ============ tf32 MMA GEMM: BM=128, BN=128, BK=32, 256 thr (8 warps 4x2) ===
struct MmaSmem { uint a[128 * 32]; uint b[128 * 32]; };

__device__ __forceinline__ void mma_chunk(MmaSmem& sm, int wm, int wn, int lane,
                                          float acc[2][8][4]) {
#pragma unroll
    for (int kt = 0; kt < 4; kt++) {
        uint4 a0u = *reinterpret_cast<uint4*>(&sm.a[(((wm * 2 + 0) * 4 + kt) * 32 + lane) * 4]);
        uint4 a1u = *reinterpret_cast<uint4*>(&sm.a[(((wm * 2 + 1) * 4 + kt) * 32 + lane) * 4]);
        uint a0[4] = {a0u.x, a0u.y, a0u.z, a0u.w};
        uint a1[4] = {a1u.x, a1u.y, a1u.z, a1u.w};
#pragma unroll
        for (int j = 0; j < 8; j++) {
            uint2 bu = *reinterpret_cast<uint2*>(&sm.b[(((wn * 8 + j) * 4 + kt) * 32 + lane) * 2]);
            uint b[2] = {bu.x, bu.y};
            mma_tf32(acc[0][j], a0, b);
            mma_tf32(acc[1][j], a1, b);
        }
    }
}

// ---------- K1a: P/Q = nbr_fea @ W[:,64:192].T / W[:,192:320].T -------------
__global__ __launch_bounds__(256) void k_gemm_pq(const float* __restrict__ nbr,
                                                 const float* __restrict__ W) {
    __shared__ MmaSmem sm;
    int tid = threadIdx.x;
    int warp = tid >> 5, lane = tid & 31;
    int wm = warp >> 1, wn = warp & 1;
    int m_base = blockIdx.x * 128;
    int nb = blockIdx.y & 1, qsel = blockIdx.y >> 1;
    int koff = 64 + qsel * 128;
    int n_base = nb * 128;

    float acc[2][8][4];
#pragma unroll
    for (int i = 0; i < 2; i++)
#pragma unroll
        for (int j = 0; j < 8; j++)
#pragma unroll
            for (int k = 0; k < 4; k++) acc[i][j][k] = 0.f;

    for (int kc = 0; kc < 4; kc++) {
        int k0 = kc * 32;
#pragma unroll
        for (int it = 0; it < 4; it++) {
            int lin = it * 256 + tid;
            int row = lin >> 3, c4 = (lin & 7) * 4;
            int grow = m_base + row; if (grow >= N_EDGES) grow = N_EDGES - 1;
            float4 v = *reinterpret_cast<const float4*>(nbr + (size_t)grow * 128 + k0 + c4);
            stage_a_g(sm.a, 4, row, c4 + 0, v.x);
            stage_a_g(sm.a, 4, row, c4 + 1, v.y);
            stage_a_g(sm.a, 4, row, c4 + 2, v.z);
            stage_a_g(sm.a, 4, row, c4 + 3, v.w);
        }
#pragma unroll
        for (int it = 0; it < 4; it++) {
            int lin = it * 256 + tid;
            int row = lin >> 3, c4 = (lin & 7) * 4;
            float4 v = *reinterpret_cast<const float4*>(W + (size_t)(n_base + row) * 320 + koff + k0 + c4);
            stage_b_g(sm.b, 4, row, c4 + 0, v.x);
            stage_b_g(sm.b, 4, row, c4 + 1, v.y);
            stage_b_g(sm.b, 4, row, c4 + 2, v.z);
            stage_b_g(sm.b, 4, row, c4 + 3, v.w);
        }
        __syncthreads();
        mma_chunk(sm, wm, wn, lane, acc);
        __syncthreads();
    }
    int r = lane >> 2, cq = lane & 3;
#pragma unroll
    for (int mi = 0; mi < 2; mi++) {
        int R0 = m_base + wm * 32 + mi * 16 + r;
        int R1 = R0 + 8;
#pragma unroll
        for (int j = 0; j < 8; j++) {
            int gcol = qsel * 256 + n_base + wn * 64 + j * 8 + cq * 2;
            if (R0 < N_EDGES)
                *reinterpret_cast<__half2*>(&g_PQh[(size_t)R0 * 512 + gcol]) =
                    __floats2half2_rn(acc[mi][j][0], acc[mi][j][1]);
            if (R1 < N_EDGES)
                *reinterpret_cast<__half2*>(&g_PQh[(size_t)R1 * 512 + gcol]) =
                    __floats2half2_rn(acc[mi][j][2], acc[mi][j][3]);
        }
    }
}

// ---------- K1b: h = angle@Wa.T + P[i0] + Q[i1] -----------------------------
// Single-pass BN=256: 512 threads, 16 warps (wm 2 x wn 8), each warp 64r x 32c.
// Reads angle_fea exactly ONCE. smem: A frags 32 KB + B frags 64 KB = 96 KB.
__global__ __launch_bounds__(512) void k_gemm_angle(const float* __restrict__ ang,
                                                    const float* __restrict__ W,
                                                    const int* __restrict__ nidx) {
    extern __shared__ uint dsm[];
    uint* AF = dsm;            // 8192 uints:  KT=8, 8 m-tiles
    uint* BF = dsm + 8192;     // 16384 uints: KT=8, 32 n-tiles
    __shared__ int i0_sm[128], i1_sm[128];
    int tid = threadIdx.x;
    int warp = tid >> 5, lane = tid & 31;
    int wm = warp >> 3, wn = warp & 7;
    int m_base = blockIdx.x * 128;

    if (tid < 128) {
        i0_sm[tid] = nidx[(m_base + tid) * 2 + 0];
        i1_sm[tid] = nidx[(m_base + tid) * 2 + 1];
    }

    // stage A: 128 rows x 64 cols (angle_fea, streamed once)
#pragma unroll
    for (int it = 0; it < 4; it++) {
        int lin = it * 512 + tid;
        int row = lin >> 4, c4 = (lin & 15) * 4;
        float4 v = ldcs_f4(ang + (size_t)(m_base + row) * 64 + c4);
        stage_a_g(AF, 8, row, c4 + 0, v.x);
        stage_a_g(AF, 8, row, c4 + 1, v.y);
        stage_a_g(AF, 8, row, c4 + 2, v.z);
        stage_a_g(AF, 8, row, c4 + 3, v.w);
    }
    // stage B: ALL 256 weight rows x 64 cols
#pragma unroll
    for (int it = 0; it < 8; it++) {
        int lin = it * 512 + tid;
        int row = lin >> 4, c4 = (lin & 15) * 4;
        float4 v = *reinterpret_cast<const float4*>(W + (size_t)row * 320 + c4);
        stage_b_g(BF, 8, row, c4 + 0, v.x);
        stage_b_g(BF, 8, row, c4 + 1, v.y);
        stage_b_g(BF, 8, row, c4 + 2, v.z);
        stage_b_g(BF, 8, row, c4 + 3, v.w);
    }
    __syncthreads();

    float acc[4][4][4];
#pragma unroll
    for (int i = 0; i < 4; i++)
#pragma unroll
        for (int j = 0; j < 4; j++)
#pragma unroll
            for (int k = 0; k < 4; k++) acc[i][j][k] = 0.f;

#pragma unroll
    for (int kt = 0; kt < 8; kt++) {
        uint a[4][4];
#pragma unroll
        for (int mi = 0; mi < 4; mi++) {
            uint4 au = *reinterpret_cast<uint4*>(&AF[(((wm * 4 + mi) * 8 + kt) * 32 + lane) * 4]);
            a[mi][0] = au.x; a[mi][1] = au.y; a[mi][2] = au.z; a[mi][3] = au.w;
        }
#pragma unroll
        for (int nj = 0; nj < 4; nj++) {
            uint2 bu = *reinterpret_cast<uint2*>(&BF[(((wn * 4 + nj) * 8 + kt) * 32 + lane) * 2]);
            uint b[2] = {bu.x, bu.y};
#pragma unroll
            for (int mi = 0; mi < 4; mi++) mma_tf32(acc[mi][nj], a[mi], b);
        }
    }

    // epilogue: gather P/Q, add, stream h out
    int r = lane >> 2, cq = lane & 3;
#pragma unroll
    for (int mi = 0; mi < 4; mi++) {
#pragma unroll
        for (int half = 0; half < 2; half++) {
            int lr = wm * 64 + mi * 16 + r + half * 8;
            int R = m_base + lr;
            int i0 = i0_sm[lr], i1 = i1_sm[lr];
#pragma unroll
            for (int nj = 0; nj < 4; nj++) {
                int gcol = (wn * 4 + nj) * 8 + cq * 2;
                float2 p = __half22float2(*reinterpret_cast<const __half2*>(&g_PQh[(size_t)i0 * 512 + gcol]));
                float2 q = __half22float2(*reinterpret_cast<const __half2*>(&g_PQh[(size_t)i1 * 512 + 256 + gcol]));
                float v0 = acc[mi][nj][half * 2 + 0] + p.x + q.x;
                float v1 = acc[mi][nj][half * 2 + 1] + p.y + q.y;
                stcs_u32(&g_hh[(size_t)R * 256 + gcol], h2u(__floats2half2_rn(v0, v1)));
            }
        }
    }
}

// ---------- K2: crystal stats from fp16 h (sorted segments, MLP=8) ----------
__global__ __launch_bounds__(256) void k_stats(const int* __restrict__ seg) {
    __shared__ int seg_sm[128];
    int tid = threadIdx.x;
    int bi = blockIdx.x;
    if (tid < 128) seg_sm[tid] = seg[bi * 128 + tid];
    __syncthreads();
    int cp = tid & 127, halfsel = tid >> 7;
    int r0 = halfsel * 64;
    size_t rowbase = (size_t)(bi * 128 + r0);
    int cur = seg_sm[r0];
    float s0 = 0.f, s1 = 0.f, q0 = 0.f, q1 = 0.f; int c = 0;
    for (int rb = 0; rb < 64; rb += 8) {
        float2 v[8];
#pragma unroll
        for (int u = 0; u < 8; u++)
            v[u] = u2f2(ldcs_u32(&g_hh[(rowbase + rb + u) * 256 + cp * 2]));
#pragma unroll
        for (int u = 0; u < 8; u++) {
            int sg = seg_sm[r0 + rb + u];
            if (sg != cur) {
                atomicAdd(&g_sum[cur * 256 + cp * 2 + 0], s0);
                atomicAdd(&g_sum[cur * 256 + cp * 2 + 1], s1);
                atomicAdd(&g_sumsq[cur * 256 + cp * 2 + 0], q0);
                atomicAdd(&g_sumsq[cur * 256 + cp * 2 + 1], q1);
                if (cp == 0) atomicAdd(&g_cnt[cur], c);
                s0 = s1 = q0 = q1 = 0.f; c = 0; cur = sg;
            }
            s0 += v[u].x; q0 += v[u].x * v[u].x;
            s1 += v[u].y; q1 += v[u].y * v[u].y;
            c++;
        }
    }
    atomicAdd(&g_sum[cur * 256 + cp * 2 + 0], s0);
    atomicAdd(&g_sum[cur * 256 + cp * 2 + 1], s1);
    atomicAdd(&g_sumsq[cur * 256 + cp * 2 + 0], q0);
    atomicAdd(&g_sumsq[cur * 256 + cp * 2 + 1], q1);
    if (cp == 0) atomicAdd(&g_cnt[cur], c);
}

// ---------- K3: crystal-norm affine coefficients ----------------------------
__global__ void k_finalize(const float* __restrict__ gamma, const float* __restrict__ beta) {
    int c = blockIdx.x, n = threadIdx.x;
    float cnt = fmaxf((float)g_cnt[c], 1.f);
    float mean = g_sum[c * 256 + n] / cnt;
    float var = fmaxf(g_sumsq[c * 256 + n] / cnt - mean * mean, 0.f);
    float a = gamma[n] * rsqrtf(var + EPS);
    g_ca[c * 256 + n] = a;
    g_cb[c * 256 + n] = beta[n] - mean * a;
}

// ---------- K4: per-angle msg + scatter into edge sums (1 warp/angle) -------
__global__ __launch_bounds__(256) void k_msg(const int* __restrict__ seg,
                                             const int* __restrict__ nidx,
                                             const float* __restrict__ Wm,
                                             const float* __restrict__ lng,
                                             const float* __restrict__ lnb) {
    int lane = threadIdx.x & 31;
    int row = blockIdx.x * 8 + (threadIdx.x >> 5);
    const char* hbase = (const char*)&g_hh[(size_t)row * 256];
    uint2 hcu = ldcs_u64(hbase + lane * 8);
    uint2 hfu = ldcs_u64(hbase + 256 + lane * 8);
    float2 c01 = u2f2(hcu.x), c23 = u2f2(hcu.y);
    float2 f01 = u2f2(hfu.x), f23 = u2f2(hfu.y);
    float4 hc = {c01.x, c01.y, c23.x, c23.y};
    float4 hf = {f01.x, f01.y, f23.x, f23.y};
    int sg = seg[row];
    const float4* ca = reinterpret_cast<const float4*>(&g_ca[(size_t)sg * 256]);
    const float4* cb = reinterpret_cast<const float4*>(&g_cb[(size_t)sg * 256]);
    float4 ac = ca[lane], af = ca[32 + lane];
    float4 bc = cb[lane], bf = cb[32 + lane];
    float4 core, filt;
    core.x = hc.x * ac.x + bc.x; core.y = hc.y * ac.y + bc.y;
    core.z = hc.z * ac.z + bc.z; core.w = hc.w * ac.w + bc.w;
    filt.x = hf.x * af.x + bf.x; filt.y = hf.y * af.y + bf.y;
    filt.z = hf.z * af.z + bf.z; filt.w = hf.w * af.w + bf.w;
    float s1 = core.x + core.y + core.z + core.w;
    float s2 = core.x * core.x + core.y * core.y + core.z * core.z + core.w * core.w;
#pragma unroll
    for (int off = 16; off >= 1; off >>= 1) {
        s1 += __shfl_xor_sync(0xffffffffu, s1, off);
        s2 += __shfl_xor_sync(0xffffffffu, s2, off);
    }
    float mean = s1 * (1.f / 128.f);
    float var = fmaxf(s2 * (1.f / 128.f) - mean * mean, 0.f);
    float rstd = rsqrtf(var + EPS);
    float4 g4 = reinterpret_cast<const float4*>(lng)[lane];
    float4 b4 = reinterpret_cast<const float4*>(lnb)[lane];
    float4 sl;
    sl.x = silu_f((core.x - mean) * rstd * g4.x + b4.x);
    sl.y = silu_f((core.y - mean) * rstd * g4.y + b4.y);
    sl.z = silu_f((core.z - mean) * rstd * g4.z + b4.z);
    sl.w = silu_f((core.w - mean) * rstd * g4.w + b4.w);
    float4 wm = reinterpret_cast<const float4*>(Wm)[lane];
    float gp = filt.x * wm.x + filt.y * wm.y + filt.z * wm.z + filt.w * wm.w;
#pragma unroll
    for (int off = 16; off >= 1; off >>= 1) gp += __shfl_xor_sync(0xffffffffu, gp, off);
    float gate = 1.f / (1.f + __expf(-gp));
    float4 msg = {gate * sl.x, gate * sl.y, gate * sl.z, gate * sl.w};
    int src = nidx[row * 2];
    float* dst = &g_s[(size_t)src * 128 + lane * 4];
    asm volatile("red.global.add.v4.f32 [%0], {%1,%2,%3,%4};"
                 :: "l"(dst), "f"(msg.x), "f"(msg.y), "f"(msg.z), "f"(msg.w) : "memory");
    if (lane == 0) atomicAdd(&g_ecnt[src], 1);
}

// ---------- K5: per-edge LN2 + two residual MLPs, tf32 tensor cores ---------
__global__ __launch_bounds__(512) void k_edge(const float* __restrict__ nbr,
                       const float* __restrict__ ln2g, const float* __restrict__ ln2b,
                       const float* __restrict__ W1a, const float* __restrict__ b1a,
                       const float* __restrict__ W2a, const float* __restrict__ b2a,
                       const float* __restrict__ W1b, const float* __restrict__ b1b,
                       const float* __restrict__ W2b, const float* __restrict__ b2b,
                       float* __restrict__ out) {
    extern __shared__ uint usm[];
    uint* W1AF = usm;
    uint* W2AF = usm + 8192;
    uint* W1BF = usm + 16384;
    uint* W2BF = usm + 24576;
    uint* XF   = usm + 32768;
    uint* H1F  = usm + 36864;
    float* x_sm = (float*)(usm + 38912);
    float* bias = (float*)(usm + 43008);
    float* b1as = bias;
    float* b2as = bias + 64;
    float* b1bs = bias + 192;
    float* b2bs = bias + 256;
    float* g2s  = bias + 384;
    float* bb2s = bias + 512;

    int tid = threadIdx.x;
    int wid = tid >> 5, lane = tid & 31;
    int r = lane >> 2, cq = lane & 3;

    for (int i = tid; i < 8192; i += 512) {
        int j = i >> 7, d = i & 127;
        stage_b_g(W1AF, 16, j, d, W1a[i]);
        stage_b_g(W1BF, 16, j, d, W1b[i]);
        int d2 = i >> 6, j2 = i & 63;
        stage_b_g(W2AF, 8, d2, j2, W2a[i]);
        stage_b_g(W2BF, 8, d2, j2, W2b[i]);
    }
    if (tid < 64) { b1as[tid] = b1a[tid]; bias[192 + tid] = b1b[tid]; }
    else if (tid >= 128 && tid < 256) {
        int t = tid - 128;
        b2as[t] = b2a[t]; b2bs[t] = b2b[t]; g2s[t] = ln2g[t]; bb2s[t] = ln2b[t];
    }
    __syncthreads();

    int mt = wid >> 3;
    int ntw = wid & 7;

    for (int grp = blockIdx.x; grp < N_EDGES / 32; grp += gridDim.x) {
        int e_base = grp * 32;
        {
            int eL = tid >> 4, l16 = tid & 15;
            int e = e_base + eL;
            float inv = 1.f / fmaxf((float)g_ecnt[e], 1.f);
            float4 v0 = ldcs_f4(&g_s[(size_t)e * 128 + l16 * 8]);
            float4 v1 = ldcs_f4(&g_s[(size_t)e * 128 + l16 * 8 + 4]);
            float vals[8] = {v0.x * inv, v0.y * inv, v0.z * inv, v0.w * inv,
                             v1.x * inv, v1.y * inv, v1.z * inv, v1.w * inv};
            float s1 = 0.f, s2 = 0.f;
#pragma unroll
            for (int k = 0; k < 8; k++) { s1 += vals[k]; s2 += vals[k] * vals[k]; }
#pragma unroll
            for (int off = 8; off >= 1; off >>= 1) {
                s1 += __shfl_xor_sync(0xffffffffu, s1, off);
                s2 += __shfl_xor_sync(0xffffffffu, s2, off);
            }
            float mean = s1 * (1.f / 128.f);
            float var = fmaxf(s2 * (1.f / 128.f) - mean * mean, 0.f);
            float rstd = rsqrtf(var + EPS);
            int d0 = l16 * 8;
#pragma unroll
            for (int k = 0; k < 8; k++) {
                float xv = (vals[k] - mean) * rstd * g2s[d0 + k] + bb2s[d0 + k];
                x_sm[eL * 128 + d0 + k] = xv;
                stage_a_g(XF, 16, eL, d0 + k, xv);
            }
        }
        __syncthreads();
        {
            float c[4] = {0.f, 0.f, 0.f, 0.f};
#pragma unroll
            for (int kt = 0; kt < 16; kt++) {
                uint4 au = *reinterpret_cast<uint4*>(&XF[((mt * 16 + kt) * 32 + lane) * 4]);
                uint a[4] = {au.x, au.y, au.z, au.w};
                uint2 bu = *reinterpret_cast<uint2*>(&W1AF[((ntw * 16 + kt) * 32 + lane) * 2]);
                uint b[2] = {bu.x, bu.y};
                mma_tf32(c, a, b);
            }
            int col = ntw * 8 + cq * 2;
            int row0 = mt * 16 + r, row1 = row0 + 8;
            stage_a_g(H1F, 8, row0, col,     silu_f(c[0] + b1as[col]));
            stage_a_g(H1F, 8, row0, col + 1, silu_f(c[1] + b1as[col + 1]));
            stage_a_g(H1F, 8, row1, col,     silu_f(c[2] + b1as[col]));
            stage_a_g(H1F, 8, row1, col + 1, silu_f(c[3] + b1as[col + 1]));
        }
        __syncthreads();
        {
#pragma unroll
            for (int t = 0; t < 2; t++) {
                int nt2 = ntw + t * 8;
                float c[4] = {0.f, 0.f, 0.f, 0.f};
#pragma unroll
                for (int kt = 0; kt < 8; kt++) {
                    uint4 au = *reinterpret_cast<uint4*>(&H1F[((mt * 8 + kt) * 32 + lane) * 4]);
                    uint a[4] = {au.x, au.y, au.z, au.w};
                    uint2 bu = *reinterpret_cast<uint2*>(&W2AF[((nt2 * 8 + kt) * 32 + lane) * 2]);
                    uint b[2] = {bu.x, bu.y};
                    mma_tf32(c, a, b);
                }
                int col = nt2 * 8 + cq * 2;
                int row0 = mt * 16 + r, row1 = row0 + 8;
                float n00 = x_sm[row0 * 128 + col]     + c[0] + b2as[col];
                float n01 = x_sm[row0 * 128 + col + 1] + c[1] + b2as[col + 1];
                float n10 = x_sm[row1 * 128 + col]     + c[2] + b2as[col];
                float n11 = x_sm[row1 * 128 + col + 1] + c[3] + b2as[col + 1];
                x_sm[row0 * 128 + col] = n00;     x_sm[row0 * 128 + col + 1] = n01;
                x_sm[row1 * 128 + col] = n10;     x_sm[row1 * 128 + col + 1] = n11;
                stage_a_g(XF, 16, row0, col, n00); stage_a_g(XF, 16, row0, col + 1, n01);
                stage_a_g(XF, 16, row1, col, n10); stage_a_g(XF, 16, row1, col + 1, n11);
            }
        }
        __syncthreads();
        {
            float c[4] = {0.f, 0.f, 0.f, 0.f};
#pragma unroll
            for (int kt = 0; kt < 16; kt++) {
                uint4 au = *reinterpret_cast<uint4*>(&XF[((mt * 16 + kt) * 32 + lane) * 4]);
                uint a[4] = {au.x, au.y, au.z, au.w};
                uint2 bu = *reinterpret_cast<uint2*>(&W1BF[((ntw * 16 + kt) * 32 + lane) * 2]);
                uint b[2] = {bu.x, bu.y};
                mma_tf32(c, a, b);
            }
            int col = ntw * 8 + cq * 2;
            int row0 = mt * 16 + r, row1 = row0 + 8;
            stage_a_g(H1F, 8, row0, col,     silu_f(c[0] + bias[192 + col]));
            stage_a_g(H1F, 8, row0, col + 1, silu_f(c[1] + bias[192 + col + 1]));
            stage_a_g(H1F, 8, row1, col,     silu_f(c[2] + bias[192 + col]));
            stage_a_g(H1F, 8, row1, col + 1, silu_f(c[3] + bias[192 + col + 1]));
        }
        __syncthreads();
        {
#pragma unroll
            for (int t = 0; t < 2; t++) {
                int nt2 = ntw + t * 8;
                float c[4] = {0.f, 0.f, 0.f, 0.f};
#pragma unroll
                for (int kt = 0; kt < 8; kt++) {
                    uint4 au = *reinterpret_cast<uint4*>(&H1F[((mt * 8 + kt) * 32 + lane) * 4]);
                    uint a[4] = {au.x, au.y, au.z, au.w};
                    uint2 bu = *reinterpret_cast<uint2*>(&W2BF[((nt2 * 8 + kt) * 32 + lane) * 2]);
                    uint b[2] = {bu.x, bu.y};
                    mma_tf32(c, a, b);
                }
                int col = nt2 * 8 + cq * 2;
                int row0 = mt * 16 + r, row1 = row0 + 8;
                int e0 = e_base + row0, e1 = e_base + row1;
                float f00 = x_sm[row0 * 128 + col]     + c[0] + b2bs[col];
                float f01 = x_sm[row0 * 128 + col + 1] + c[1] + b2bs[col + 1];
                float f10 = x_sm[row1 * 128 + col]     + c[2] + b2bs[col];
                float f11 = x_sm[row1 * 128 + col + 1] + c[3] + b2bs[col + 1];
                float2 nb0 = ldcs_f2(&nbr[(size_t)e0 * 128 + col]);
                float2 nb1 = ldcs_f2(&nbr[(size_t)e1 * 128 + col]);
                float2 o0 = {INV_SQRT_2 * (nb0.x + f00), INV_SQRT_2 * (nb0.y + f01)};
                float2 o1 = {INV_SQRT_2 * (nb1.x + f10), INV_SQRT_2 * (nb1.y + f11)};
                stcs_f2(&out[(size_t)e0 * 128 + col], o0);
                stcs_f2(&out[(size_t)e1 * 128 + col], o1);
            }
        }
        __syncthreads();
    }
}

// ---------- launch ----------------------------------------------------------
extern "C" void kernel_launch(void* const* d_in, const int* in_sizes, int n_in,
                              void* d_out, int out_size) {
    const float* nbr_fea   = (const float*)d_in[0];
    const float* angle_fea = (const float*)d_in[1];
    const int*   nidx      = (const int*)d_in[2];
    const int*   cai       = (const int*)d_in[4];
    const float* W_full    = (const float*)d_in[5];
    const float* W_mask    = (const float*)d_in[6];
    const float* cn_gamma  = (const float*)d_in[7];
    const float* cn_beta   = (const float*)d_in[8];
    const float* ln_core_g = (const float*)d_in[9];
    const float* ln_core_b = (const float*)d_in[10];
    const float* ln2_g     = (const float*)d_in[11];
    const float* ln2_b     = (const float*)d_in[12];
    const float* res_W1a   = (const float*)d_in[13];
    const float* res_b1a   = (const float*)d_in[14];
    const float* res_W2a   = (const float*)d_in[15];
    const float* res_b2a   = (const float*)d_in[16];
    const float* res_W1b   = (const float*)d_in[17];
    const float* res_b1b   = (const float*)d_in[18];
    const float* res_W2b   = (const float*)d_in[19];
    const float* res_b2b   = (const float*)d_in[20];
    float* out = (float*)d_out;

    static bool attr_set = false;
    if (!attr_set) {
        cudaFuncSetAttribute(k_edge, cudaFuncAttributeMaxDynamicSharedMemorySize, 176 * 1024);
        cudaFuncSetAttribute(k_gemm_angle, cudaFuncAttributeMaxDynamicSharedMemorySize, 100 * 1024);
        attr_set = true;
    }

    k_zero<<<1024, 256>>>();
    k_gemm_pq<<<dim3((N_EDGES + 127) / 128, 4), 256>>>(nbr_fea, W_full);
    k_gemm_angle<<<N_ANGLES / 128, 512, 98304>>>(angle_fea, W_full, nidx);
    k_stats<<<N_ANGLES / 128, 256>>>(cai);
    k_finalize<<<N_CRYST, 256>>>(cn_gamma, cn_beta);
    k_msg<<<N_ANGLES / 8, 256>>>(cai, nidx, W_mask, ln_core_g, ln_core_b);
    k_edge<<<148, 512, 43648 * sizeof(float)>>>(nbr_fea, ln2_g, ln2_b,
                                                res_W1a, res_b1a, res_W2a, res_b2a,
                                                res_W1b, res_b1b, res_W2b, res_b2b, out);
}